// round 1
// baseline (speedup 1.0000x reference)
#include <cuda_runtime.h>
#include <cstddef>

#define N_ITEM 81920
#define E_INT 327680
#define N_TGT 2048
#define NUM_NODE 50000
#define DIM 256
#define NPOS 200
#define ALPHA 0.2f

// ---------------- device scratch (static, no allocation) ----------------
__device__ __align__(16) float g_ft[(size_t)N_ITEM * DIM];   // 84 MB
__device__ int   g_deg[N_ITEM];
__device__ int   g_rowoff[N_ITEM + 1];
__device__ int   g_cursor[N_ITEM];
__device__ int   g_perm[E_INT];
__device__ int   g_adeg[N_TGT];
__device__ int   g_arowoff[N_TGT + 1];
__device__ int   g_acursor[N_TGT];
__device__ int   g_aperm[N_ITEM];
__device__ __align__(16) float g_B[NPOS * DIM];
__device__ float g_coef[N_ITEM];
__device__ __align__(16) float g_select[N_TGT * DIM];

// ---------------- init ----------------
__global__ void k_zero() {
    int i = blockIdx.x * blockDim.x + threadIdx.x;
    if (i < N_ITEM) g_deg[i] = 0;
    if (i < N_TGT)  g_adeg[i] = 0;
}

// ---------------- histograms ----------------
__global__ void k_hist(const int* __restrict__ i_dst, const int* __restrict__ agg_dst) {
    int i = blockIdx.x * blockDim.x + threadIdx.x;
    if (i < E_INT)  atomicAdd(&g_deg[i_dst[i]], 1);
    if (i < N_ITEM) atomicAdd(&g_adeg[agg_dst[i]], 1);
}

// ---------------- single-block exclusive scan (n <= 1024*per) ----------------
__global__ void k_scan(int which) {
    const int* deg; int* rowoff; int* cursor; int n;
    if (which == 0) { deg = g_deg;  rowoff = g_rowoff;  cursor = g_cursor;  n = N_ITEM; }
    else            { deg = g_adeg; rowoff = g_arowoff; cursor = g_acursor; n = N_TGT;  }

    __shared__ int s[1024];
    int t = threadIdx.x;
    int per = (n + 1023) / 1024;
    int st = t * per;
    int en = st + per; if (en > n) en = n;
    int sum = 0;
    for (int i = st; i < en; i++) sum += deg[i];
    s[t] = sum;
    __syncthreads();
    for (int off = 1; off < 1024; off <<= 1) {
        int v = (t >= off) ? s[t - off] : 0;
        __syncthreads();
        if (t >= off) s[t] += v;
        __syncthreads();
    }
    int run = (t == 0) ? 0 : s[t - 1];
    for (int i = st; i < en; i++) {
        rowoff[i] = run; cursor[i] = run; run += deg[i];
    }
    if (t == 1023) rowoff[n] = s[1023];
}

// ---------------- scatter edge ids into CSR ----------------
__global__ void k_scatter(const int* __restrict__ i_dst, const int* __restrict__ agg_dst) {
    int i = blockIdx.x * blockDim.x + threadIdx.x;
    if (i < E_INT) {
        int d = i_dst[i];
        int p = atomicAdd(&g_cursor[d], 1);
        g_perm[p] = i;
    }
    if (i < N_ITEM) {
        int d = agg_dst[i];
        int p = atomicAdd(&g_acursor[d], 1);
        g_aperm[p] = i;
    }
}

// ---------------- attention + softmax + weighted aggregation (warp per dst) ----------------
__global__ void __launch_bounds__(256) k_attn(const int* __restrict__ iid,
                                              const int* __restrict__ i_src,
                                              const float* __restrict__ emb,
                                              const float* __restrict__ p_w) {
    int gw   = (blockIdx.x * blockDim.x + threadIdx.x) >> 5;
    int lane = threadIdx.x & 31;
    if (gw >= N_ITEM) return;
    int v = gw;
    const float4* embv = (const float4*)emb;
    int c0 = lane * 2;  // two float4 per lane -> dims [lane*8, lane*8+8)

    size_t rv = (size_t)iid[v] * (DIM / 4);
    float4 hd0 = embv[rv + c0];
    float4 hd1 = embv[rv + c0 + 1];
    float4 pw0 = ((const float4*)p_w)[c0];
    float4 pw1 = ((const float4*)p_w)[c0 + 1];

    int rs = g_rowoff[v], re = g_rowoff[v + 1];

    // pass 1: max logit
    float m = -1e30f;
    for (int idx = rs; idx < re; idx++) {
        int e = g_perm[idx];
        size_t ru = (size_t)iid[i_src[e]] * (DIM / 4);
        float4 hs0 = embv[ru + c0];
        float4 hs1 = embv[ru + c0 + 1];
        float p = hs0.x*hd0.x*pw0.x + hs0.y*hd0.y*pw0.y + hs0.z*hd0.z*pw0.z + hs0.w*hd0.w*pw0.w
                + hs1.x*hd1.x*pw1.x + hs1.y*hd1.y*pw1.y + hs1.z*hd1.z*pw1.z + hs1.w*hd1.w*pw1.w;
        #pragma unroll
        for (int o = 16; o; o >>= 1) p += __shfl_xor_sync(0xffffffffu, p, o);
        p = (p >= 0.f) ? p : ALPHA * p;
        m = fmaxf(m, p);
    }

    // pass 2: exp-sum + weighted sum (recompute logits; emb is L2-resident)
    float den = 0.f;
    float4 a0 = make_float4(0.f, 0.f, 0.f, 0.f);
    float4 a1 = make_float4(0.f, 0.f, 0.f, 0.f);
    for (int idx = rs; idx < re; idx++) {
        int e = g_perm[idx];
        size_t ru = (size_t)iid[i_src[e]] * (DIM / 4);
        float4 hs0 = embv[ru + c0];
        float4 hs1 = embv[ru + c0 + 1];
        float p = hs0.x*hd0.x*pw0.x + hs0.y*hd0.y*pw0.y + hs0.z*hd0.z*pw0.z + hs0.w*hd0.w*pw0.w
                + hs1.x*hd1.x*pw1.x + hs1.y*hd1.y*pw1.y + hs1.z*hd1.z*pw1.z + hs1.w*hd1.w*pw1.w;
        #pragma unroll
        for (int o = 16; o; o >>= 1) p += __shfl_xor_sync(0xffffffffu, p, o);
        p = (p >= 0.f) ? p : ALPHA * p;
        float ex = __expf(p - m) == 0.f ? expf(p - m) : expf(p - m); // use accurate expf
        den += ex;
        a0.x += ex * hs0.x; a0.y += ex * hs0.y; a0.z += ex * hs0.z; a0.w += ex * hs0.w;
        a1.x += ex * hs1.x; a1.y += ex * hs1.y; a1.z += ex * hs1.z; a1.w += ex * hs1.w;
    }
    float inv = 1.f / fmaxf(den, 1e-12f);
    float4 o0 = make_float4(a0.x * inv, a0.y * inv, a0.z * inv, a0.w * inv);
    float4 o1 = make_float4(a1.x * inv, a1.y * inv, a1.z * inv, a1.w * inv);
    ((float4*)g_ft)[(size_t)v * (DIM / 4) + c0]     = o0;
    ((float4*)g_ft)[(size_t)v * (DIM / 4) + c0 + 1] = o1;
}

// ---------------- B = pos_emb @ q_w[:,256:].T  (200x256) ----------------
__global__ void k_posB(const float* __restrict__ pos_emb, const float* __restrict__ q_w) {
    int p = blockIdx.x;
    int d = threadIdx.x;
    __shared__ float sp[DIM];
    sp[d] = pos_emb[p * DIM + d];
    __syncthreads();
    const float4* q4 = (const float4*)(q_w + (size_t)d * (2 * DIM) + DIM);
    float acc = 0.f;
    #pragma unroll 8
    for (int k = 0; k < DIM / 4; k++) {
        float4 q = q4[k];
        acc += sp[4*k] * q.x + sp[4*k+1] * q.y + sp[4*k+2] * q.z + sp[4*k+3] * q.w;
    }
    g_B[p * DIM + d] = acc;
}

// ---------------- coef: y = ft@q1.T + B[pid]; coef = sum(tanh(y)*h_t) ----------------
#define CJ 64
__global__ void __launch_bounds__(256) k_coef(const int* __restrict__ agg_src,
                                              const int* __restrict__ pid,
                                              const int* __restrict__ agg_dst,
                                              const int* __restrict__ tid,
                                              const float* __restrict__ tgt_emb,
                                              const float* __restrict__ q_w) {
    __shared__ float As[CJ][33];      // ft rows   [row][k]
    __shared__ float Qs[DIM][33];     // q1        [d][k]
    __shared__ int   ssrc[CJ];
    int t = threadIdx.x;
    int j0 = blockIdx.x * CJ;
    if (t < CJ) ssrc[t] = agg_src[j0 + t];

    int w = t >> 5, l = t & 31;       // warp w -> rows w*8..w*8+7 ; lane dims l+32*dt
    float acc[8][8];
    #pragma unroll
    for (int a = 0; a < 8; a++)
        #pragma unroll
        for (int b = 0; b < 8; b++) acc[a][b] = 0.f;

    for (int kc = 0; kc < DIM; kc += 32) {
        __syncthreads();
        for (int i = t; i < CJ * 32; i += 256) {
            int r = i >> 5, kk = i & 31;
            As[r][kk] = g_ft[(size_t)ssrc[r] * DIM + kc + kk];
        }
        for (int i = t; i < DIM * 32; i += 256) {
            int d = i >> 5, kk = i & 31;
            Qs[d][kk] = q_w[(size_t)d * (2 * DIM) + kc + kk];
        }
        __syncthreads();
        #pragma unroll
        for (int kk = 0; kk < 32; kk++) {
            float a[8], q[8];
            #pragma unroll
            for (int jj = 0; jj < 8; jj++) a[jj] = As[w * 8 + jj][kk];
            #pragma unroll
            for (int dt = 0; dt < 8; dt++) q[dt] = Qs[l + 32 * dt][kk];
            #pragma unroll
            for (int jj = 0; jj < 8; jj++)
                #pragma unroll
                for (int dt = 0; dt < 8; dt++) acc[jj][dt] += a[jj] * q[dt];
        }
    }

    #pragma unroll
    for (int jj = 0; jj < 8; jj++) {
        int j = j0 + w * 8 + jj;
        const float* Brow = g_B + (size_t)pid[j] * DIM;
        const float* ht   = tgt_emb + (size_t)tid[agg_dst[j]] * DIM;
        float c = 0.f;
        #pragma unroll
        for (int dt = 0; dt < 8; dt++) {
            int d = l + 32 * dt;
            float y = tanhf(acc[jj][dt] + Brow[d]);
            c += y * ht[d];
        }
        #pragma unroll
        for (int o = 16; o; o >>= 1) c += __shfl_xor_sync(0xffffffffu, c, o);
        if (l == 0) g_coef[j] = c;
    }
}

// ---------------- select[t] = sum_{j in CSR(t)} coef[j]*ft[agg_src[j]] ----------------
__global__ void k_select(const int* __restrict__ agg_src) {
    int tgt = blockIdx.x;
    int d = threadIdx.x;
    float acc = 0.f;
    int rs = g_arowoff[tgt], re = g_arowoff[tgt + 1];
    for (int idx = rs; idx < re; idx++) {
        int j = g_aperm[idx];
        acc += g_coef[j] * g_ft[(size_t)agg_src[j] * DIM + d];
    }
    g_select[tgt * DIM + d] = acc;
}

// ---------------- scores = select @ emb[1:].T  (2048 x 49999, K=256) ----------------
#define GM 128
#define GN 128
#define GK 16
__global__ void __launch_bounds__(256) k_scores(const float* __restrict__ emb,
                                                float* __restrict__ out) {
    __shared__ __align__(16) float As[GK][GM];
    __shared__ __align__(16) float Bs[GK][GN];
    int t = threadIdx.x;
    int bm = blockIdx.y * GM;  // target-row tile
    int bn = blockIdx.x * GN;  // item-col tile
    int tr = (t >> 4) * 8;
    int tc = (t & 15) * 8;
    float acc[8][8];
    #pragma unroll
    for (int i = 0; i < 8; i++)
        #pragma unroll
        for (int j = 0; j < 8; j++) acc[i][j] = 0.f;

    for (int kc = 0; kc < DIM; kc += GK) {
        __syncthreads();
        #pragma unroll
        for (int i = 0; i < 2; i++) {
            int id = t + 256 * i;             // 0..511 float4 tasks
            int row = id & 127, c4 = id >> 7; // c4 in 0..3
            float4 v = *(const float4*)(g_select + (size_t)(bm + row) * DIM + kc + c4 * 4);
            As[c4*4+0][row] = v.x; As[c4*4+1][row] = v.y;
            As[c4*4+2][row] = v.z; As[c4*4+3][row] = v.w;
        }
        #pragma unroll
        for (int i = 0; i < 2; i++) {
            int id = t + 256 * i;
            int col = id & 127, c4 = id >> 7;
            int er = bn + col + 1;            // emb row (skip row 0)
            float4 v;
            if (er < NUM_NODE) v = *(const float4*)(emb + (size_t)er * DIM + kc + c4 * 4);
            else               v = make_float4(0.f, 0.f, 0.f, 0.f);
            Bs[c4*4+0][col] = v.x; Bs[c4*4+1][col] = v.y;
            Bs[c4*4+2][col] = v.z; Bs[c4*4+3][col] = v.w;
        }
        __syncthreads();
        #pragma unroll
        for (int kk = 0; kk < GK; kk++) {
            float a[8], b[8];
            *(float4*)&a[0] = *(const float4*)&As[kk][tr];
            *(float4*)&a[4] = *(const float4*)&As[kk][tr + 4];
            *(float4*)&b[0] = *(const float4*)&Bs[kk][tc];
            *(float4*)&b[4] = *(const float4*)&Bs[kk][tc + 4];
            #pragma unroll
            for (int i = 0; i < 8; i++)
                #pragma unroll
                for (int j = 0; j < 8; j++) acc[i][j] += a[i] * b[j];
        }
    }

    const int NC = NUM_NODE - 1;  // 49999 (odd stride -> scalar stores)
    #pragma unroll
    for (int i = 0; i < 8; i++) {
        int row = bm + tr + i;
        size_t base = (size_t)row * NC + bn + tc;
        #pragma unroll
        for (int j = 0; j < 8; j++) {
            if (bn + tc + j < NC) out[base + j] = acc[i][j];
        }
    }
}

// ---------------- launch ----------------
extern "C" void kernel_launch(void* const* d_in, const int* in_sizes, int n_in,
                              void* d_out, int out_size) {
    const int*   iid     = (const int*)d_in[2];
    const int*   pid     = (const int*)d_in[3];
    const int*   tidp    = (const int*)d_in[4];
    const int*   i_src   = (const int*)d_in[5];
    const int*   i_dst   = (const int*)d_in[6];
    const int*   agg_src = (const int*)d_in[7];
    const int*   agg_dst = (const int*)d_in[8];
    const float* emb     = (const float*)d_in[9];
    const float* pos_emb = (const float*)d_in[10];
    const float* tgt_emb = (const float*)d_in[11];
    const float* p_w     = (const float*)d_in[12];
    const float* q_w     = (const float*)d_in[13];
    float* out = (float*)d_out;

    k_zero   <<<(N_ITEM + 255) / 256, 256>>>();
    k_hist   <<<(E_INT + 255) / 256, 256>>>(i_dst, agg_dst);
    k_scan   <<<1, 1024>>>(0);
    k_scan   <<<1, 1024>>>(1);
    k_scatter<<<(E_INT + 255) / 256, 256>>>(i_dst, agg_dst);
    k_attn   <<<N_ITEM / 8, 256>>>(iid, i_src, emb, p_w);
    k_posB   <<<NPOS, 256>>>(pos_emb, q_w);
    k_coef   <<<N_ITEM / CJ, 256>>>(agg_src, pid, agg_dst, tidp, tgt_emb, q_w);
    k_select <<<N_TGT, 256>>>(agg_src);
    dim3 g((NUM_NODE - 1 + GN - 1) / GN, N_TGT / GM);
    k_scores <<<g, 256>>>(emb, out);
}

// round 4
// speedup vs baseline: 1.7019x; 1.7019x over previous
#include <cuda_runtime.h>
#include <cuda_bf16.h>
#include <cstdint>
#include <cstddef>

#define N_ITEM 81920
#define E_INT 327680
#define N_TGT 2048
#define NUM_NODE 50000
#define DIM 256
#define NPOS 200
#define ALPHA 0.2f

// ---------------- device scratch (static, no allocation) ----------------
__device__ __align__(16) float g_ft[(size_t)N_ITEM * DIM];   // 84 MB
__device__ int   g_deg[N_ITEM];
__device__ int   g_rowoff[N_ITEM + 1];
__device__ int   g_cursor[N_ITEM];
__device__ int   g_perm[E_INT];
__device__ int   g_adeg[N_TGT];
__device__ int   g_arowoff[N_TGT + 1];
__device__ int   g_acursor[N_TGT];
__device__ int   g_aperm[N_ITEM];
__device__ __align__(16) float g_B[NPOS * DIM];
__device__ float g_coef[N_ITEM];
// hi/lo bf16 splits for tensor-core GEMM
__device__ __align__(16) __nv_bfloat16 g_emb_hi[(size_t)NUM_NODE * DIM];
__device__ __align__(16) __nv_bfloat16 g_emb_lo[(size_t)NUM_NODE * DIM];
__device__ __align__(16) __nv_bfloat16 g_sel_hi[N_TGT * DIM];
__device__ __align__(16) __nv_bfloat16 g_sel_lo[N_TGT * DIM];

__device__ __forceinline__ uint32_t smem_to_u32(const void* p) {
    uint32_t a;
    asm("{ .reg .u64 t; cvta.to.shared.u64 t, %1; cvt.u32.u64 %0, t; }" : "=r"(a) : "l"(p));
    return a;
}

// ---------------- init ----------------
__global__ void k_zero() {
    int i = blockIdx.x * blockDim.x + threadIdx.x;
    if (i < N_ITEM) g_deg[i] = 0;
    if (i < N_TGT)  g_adeg[i] = 0;
}

// ---------------- split emb into bf16 hi/lo ----------------
__global__ void k_split_emb(const float* __restrict__ emb) {
    size_t i = (size_t)blockIdx.x * blockDim.x + threadIdx.x;
    if (i >= (size_t)NUM_NODE * DIM) return;
    float x = emb[i];
    __nv_bfloat16 h = __float2bfloat16(x);
    g_emb_hi[i] = h;
    g_emb_lo[i] = __float2bfloat16(x - __bfloat162float(h));
}

// ---------------- histograms ----------------
__global__ void k_hist(const int* __restrict__ i_dst, const int* __restrict__ agg_dst) {
    int i = blockIdx.x * blockDim.x + threadIdx.x;
    if (i < E_INT)  atomicAdd(&g_deg[i_dst[i]], 1);
    if (i < N_ITEM) atomicAdd(&g_adeg[agg_dst[i]], 1);
}

// ---------------- single-block exclusive scan ----------------
__global__ void k_scan(int which) {
    const int* deg; int* rowoff; int* cursor; int n;
    if (which == 0) { deg = g_deg;  rowoff = g_rowoff;  cursor = g_cursor;  n = N_ITEM; }
    else            { deg = g_adeg; rowoff = g_arowoff; cursor = g_acursor; n = N_TGT;  }
    __shared__ int s[1024];
    int t = threadIdx.x;
    int per = (n + 1023) / 1024;
    int st = t * per, en = st + per; if (en > n) en = n;
    int sum = 0;
    for (int i = st; i < en; i++) sum += deg[i];
    s[t] = sum;
    __syncthreads();
    for (int off = 1; off < 1024; off <<= 1) {
        int v = (t >= off) ? s[t - off] : 0;
        __syncthreads();
        if (t >= off) s[t] += v;
        __syncthreads();
    }
    int run = (t == 0) ? 0 : s[t - 1];
    for (int i = st; i < en; i++) { rowoff[i] = run; cursor[i] = run; run += deg[i]; }
    if (t == 1023) rowoff[n] = s[1023];
}

// ---------------- scatter edge ids into CSR ----------------
__global__ void k_scatter(const int* __restrict__ i_dst, const int* __restrict__ agg_dst) {
    int i = blockIdx.x * blockDim.x + threadIdx.x;
    if (i < E_INT) { int d = i_dst[i]; g_perm[atomicAdd(&g_cursor[d], 1)] = i; }
    if (i < N_ITEM) { int d = agg_dst[i]; g_aperm[atomicAdd(&g_acursor[d], 1)] = i; }
}

// ---------------- attention + softmax + aggregation (warp per dst) ----------------
__global__ void __launch_bounds__(256) k_attn(const int* __restrict__ iid,
                                              const int* __restrict__ i_src,
                                              const float* __restrict__ emb,
                                              const float* __restrict__ p_w) {
    int gw   = (blockIdx.x * blockDim.x + threadIdx.x) >> 5;
    int lane = threadIdx.x & 31;
    if (gw >= N_ITEM) return;
    int v = gw;
    const float4* embv = (const float4*)emb;
    int c0 = lane * 2;
    size_t rv = (size_t)iid[v] * (DIM / 4);
    float4 hd0 = embv[rv + c0];
    float4 hd1 = embv[rv + c0 + 1];
    float4 pw0 = ((const float4*)p_w)[c0];
    float4 pw1 = ((const float4*)p_w)[c0 + 1];
    int rs = g_rowoff[v], re = g_rowoff[v + 1];

    float m = -1e30f;
    for (int idx = rs; idx < re; idx++) {
        int e = g_perm[idx];
        size_t ru = (size_t)iid[i_src[e]] * (DIM / 4);
        float4 hs0 = embv[ru + c0];
        float4 hs1 = embv[ru + c0 + 1];
        float p = hs0.x*hd0.x*pw0.x + hs0.y*hd0.y*pw0.y + hs0.z*hd0.z*pw0.z + hs0.w*hd0.w*pw0.w
                + hs1.x*hd1.x*pw1.x + hs1.y*hd1.y*pw1.y + hs1.z*hd1.z*pw1.z + hs1.w*hd1.w*pw1.w;
        #pragma unroll
        for (int o = 16; o; o >>= 1) p += __shfl_xor_sync(0xffffffffu, p, o);
        p = (p >= 0.f) ? p : ALPHA * p;
        m = fmaxf(m, p);
    }
    float den = 0.f;
    float4 a0 = make_float4(0.f,0.f,0.f,0.f), a1 = make_float4(0.f,0.f,0.f,0.f);
    for (int idx = rs; idx < re; idx++) {
        int e = g_perm[idx];
        size_t ru = (size_t)iid[i_src[e]] * (DIM / 4);
        float4 hs0 = embv[ru + c0];
        float4 hs1 = embv[ru + c0 + 1];
        float p = hs0.x*hd0.x*pw0.x + hs0.y*hd0.y*pw0.y + hs0.z*hd0.z*pw0.z + hs0.w*hd0.w*pw0.w
                + hs1.x*hd1.x*pw1.x + hs1.y*hd1.y*pw1.y + hs1.z*hd1.z*pw1.z + hs1.w*hd1.w*pw1.w;
        #pragma unroll
        for (int o = 16; o; o >>= 1) p += __shfl_xor_sync(0xffffffffu, p, o);
        p = (p >= 0.f) ? p : ALPHA * p;
        float ex = expf(p - m);
        den += ex;
        a0.x += ex*hs0.x; a0.y += ex*hs0.y; a0.z += ex*hs0.z; a0.w += ex*hs0.w;
        a1.x += ex*hs1.x; a1.y += ex*hs1.y; a1.z += ex*hs1.z; a1.w += ex*hs1.w;
    }
    float inv = 1.f / fmaxf(den, 1e-12f);
    ((float4*)g_ft)[(size_t)v*(DIM/4) + c0]     = make_float4(a0.x*inv, a0.y*inv, a0.z*inv, a0.w*inv);
    ((float4*)g_ft)[(size_t)v*(DIM/4) + c0 + 1] = make_float4(a1.x*inv, a1.y*inv, a1.z*inv, a1.w*inv);
}

// ---------------- B = pos_emb @ q_w[:,256:].T ----------------
__global__ void k_posB(const float* __restrict__ pos_emb, const float* __restrict__ q_w) {
    int p = blockIdx.x, d = threadIdx.x;
    __shared__ float sp[DIM];
    sp[d] = pos_emb[p * DIM + d];
    __syncthreads();
    const float4* q4 = (const float4*)(q_w + (size_t)d * (2 * DIM) + DIM);
    float acc = 0.f;
    #pragma unroll 8
    for (int k = 0; k < DIM / 4; k++) {
        float4 q = q4[k];
        acc += sp[4*k]*q.x + sp[4*k+1]*q.y + sp[4*k+2]*q.z + sp[4*k+3]*q.w;
    }
    g_B[p * DIM + d] = acc;
}

// ---------------- coef ----------------
#define CJ 64
__global__ void __launch_bounds__(256) k_coef(const int* __restrict__ agg_src,
                                              const int* __restrict__ pid,
                                              const int* __restrict__ agg_dst,
                                              const int* __restrict__ tid,
                                              const float* __restrict__ tgt_emb,
                                              const float* __restrict__ q_w) {
    __shared__ float As[CJ][33];
    __shared__ float Qs[DIM][33];
    __shared__ int   ssrc[CJ];
    int t = threadIdx.x;
    int j0 = blockIdx.x * CJ;
    if (t < CJ) ssrc[t] = agg_src[j0 + t];
    int w = t >> 5, l = t & 31;
    float acc[8][8];
    #pragma unroll
    for (int a = 0; a < 8; a++)
        #pragma unroll
        for (int b = 0; b < 8; b++) acc[a][b] = 0.f;

    for (int kc = 0; kc < DIM; kc += 32) {
        __syncthreads();
        for (int i = t; i < CJ * 32; i += 256) {
            int r = i >> 5, kk = i & 31;
            As[r][kk] = g_ft[(size_t)ssrc[r] * DIM + kc + kk];
        }
        for (int i = t; i < DIM * 32; i += 256) {
            int d = i >> 5, kk = i & 31;
            Qs[d][kk] = q_w[(size_t)d * (2 * DIM) + kc + kk];
        }
        __syncthreads();
        #pragma unroll
        for (int kk = 0; kk < 32; kk++) {
            float a[8], q[8];
            #pragma unroll
            for (int jj = 0; jj < 8; jj++) a[jj] = As[w * 8 + jj][kk];
            #pragma unroll
            for (int dt = 0; dt < 8; dt++) q[dt] = Qs[l + 32 * dt][kk];
            #pragma unroll
            for (int jj = 0; jj < 8; jj++)
                #pragma unroll
                for (int dt = 0; dt < 8; dt++) acc[jj][dt] += a[jj] * q[dt];
        }
    }
    #pragma unroll
    for (int jj = 0; jj < 8; jj++) {
        int j = j0 + w * 8 + jj;
        const float* Brow = g_B + (size_t)pid[j] * DIM;
        const float* ht   = tgt_emb + (size_t)tid[agg_dst[j]] * DIM;
        float c = 0.f;
        #pragma unroll
        for (int dt = 0; dt < 8; dt++) {
            int d = l + 32 * dt;
            c += tanhf(acc[jj][dt] + Brow[d]) * ht[d];
        }
        #pragma unroll
        for (int o = 16; o; o >>= 1) c += __shfl_xor_sync(0xffffffffu, c, o);
        if (l == 0) g_coef[j] = c;
    }
}

// ---------------- select (writes bf16 hi/lo split directly) ----------------
__global__ void k_select(const int* __restrict__ agg_src) {
    int tgt = blockIdx.x;
    int d = threadIdx.x;
    float acc = 0.f;
    int rs = g_arowoff[tgt], re = g_arowoff[tgt + 1];
    for (int idx = rs; idx < re; idx++) {
        int j = g_aperm[idx];
        acc += g_coef[j] * g_ft[(size_t)agg_src[j] * DIM + d];
    }
    __nv_bfloat16 h = __float2bfloat16(acc);
    g_sel_hi[tgt * DIM + d] = h;
    g_sel_lo[tgt * DIM + d] = __float2bfloat16(acc - __bfloat162float(h));
}

// ================= scores via mma.sync bf16 hi/lo split GEMM =================
// D[2048, 49999] = select @ emb[1:].T, K=256.
// CTA tile 128x128, K-chunk 32, 2-stage cp.async pipeline.
// 8 warps = 4(m) x 2(n); warp tile 32x64 = 2 x 8 m16n8k16 tiles; 3 split products.
#define SKP 48                        // padded row length in bf16 (96B, 16B-aligned)
#define ARR_STRIDE (128 * SKP)        // bf16 elems per array
#define STAGE_STRIDE (4 * ARR_STRIDE) // bf16 elems per stage

__device__ __forceinline__ void cp16(uint32_t daddr, const void* src, uint32_t srcsize) {
    asm volatile("cp.async.cg.shared.global [%0], [%1], 16, %2;"
                 :: "r"(daddr), "l"(src), "r"(srcsize) : "memory");
}
__device__ __forceinline__ void mma_bf16(float* c, const uint32_t* a, const uint32_t* b) {
    asm volatile("mma.sync.aligned.m16n8k16.row.col.f32.bf16.bf16.f32 "
                 "{%0,%1,%2,%3}, {%4,%5,%6,%7}, {%8,%9}, {%0,%1,%2,%3};"
                 : "+f"(c[0]), "+f"(c[1]), "+f"(c[2]), "+f"(c[3])
                 : "r"(a[0]), "r"(a[1]), "r"(a[2]), "r"(a[3]), "r"(b[0]), "r"(b[1]));
}

__global__ void __launch_bounds__(256) k_scores_mma(float* __restrict__ out) {
    extern __shared__ __nv_bfloat16 sm[];
    const uint32_t sb = smem_to_u32(sm);
    const int t = threadIdx.x;
    const int wid = t >> 5, lane = t & 31;
    const int warp_m = wid & 3, warp_n = wid >> 2;
    const int bm = blockIdx.y * 128;
    const int bn = blockIdx.x * 128;
    const int NC = NUM_NODE - 1;

    const uint4* Ah4 = (const uint4*)g_sel_hi;   // 32 uint4 per 256-wide row
    const uint4* Al4 = (const uint4*)g_sel_lo;
    const uint4* Bh4 = (const uint4*)g_emb_hi;
    const uint4* Bl4 = (const uint4*)g_emb_lo;

    // ---- prefetch one stage (kc chunk) ----
    auto prefetch = [&](int stage, int kc) {
        for (int i = t; i < 2048; i += 256) {
            int arr = i >> 9;            // 0:Ah 1:Al 2:Bh 3:Bl
            int r   = (i >> 2) & 127;
            int v   = i & 3;
            uint32_t daddr = sb + 2u * (stage * STAGE_STRIDE + arr * ARR_STRIDE + r * SKP + v * 8);
            if (arr < 2) {
                size_t off = (size_t)(bm + r) * 32 + kc * 4 + v;
                cp16(daddr, (arr == 0 ? Ah4 : Al4) + off, 16);
            } else {
                int er = bn + r + 1;
                size_t off = (size_t)(er < NUM_NODE ? er : 0) * 32 + kc * 4 + v;
                cp16(daddr, (arr == 2 ? Bh4 : Bl4) + off, er < NUM_NODE ? 16u : 0u);
            }
        }
        asm volatile("cp.async.commit_group;" ::: "memory");
    };

    float c[2][8][4];
    #pragma unroll
    for (int mt = 0; mt < 2; mt++)
        #pragma unroll
        for (int nt = 0; nt < 8; nt++)
            #pragma unroll
            for (int k = 0; k < 4; k++) c[mt][nt][k] = 0.f;

    prefetch(0, 0);

    for (int kc = 0; kc < 8; kc++) {
        int s = kc & 1;
        if (kc + 1 < 8) {
            prefetch(1 - s, kc + 1);
            asm volatile("cp.async.wait_group 1;" ::: "memory");
        } else {
            asm volatile("cp.async.wait_group 0;" ::: "memory");
        }
        __syncthreads();

        const __nv_bfloat16* sAh = sm + s * STAGE_STRIDE;
        const __nv_bfloat16* sAl = sAh + ARR_STRIDE;
        const __nv_bfloat16* sBh = sAl + ARR_STRIDE;
        const __nv_bfloat16* sBl = sBh + ARR_STRIDE;

        #pragma unroll
        for (int ks = 0; ks < 2; ks++) {
            int kb = ks * 16 + (lane & 3) * 2;
            int ar = warp_m * 32 + (lane >> 2);
            int br = warp_n * 64 + (lane >> 2);

            uint32_t ah[2][4], al[2][4], bh[8][2], bl[8][2];
            #pragma unroll
            for (int mt = 0; mt < 2; mt++) {
                int r0 = ar + mt * 16;
                ah[mt][0] = *(const uint32_t*)(sAh + r0 * SKP + kb);
                ah[mt][1] = *(const uint32_t*)(sAh + (r0 + 8) * SKP + kb);
                ah[mt][2] = *(const uint32_t*)(sAh + r0 * SKP + kb + 8);
                ah[mt][3] = *(const uint32_t*)(sAh + (r0 + 8) * SKP + kb + 8);
                al[mt][0] = *(const uint32_t*)(sAl + r0 * SKP + kb);
                al[mt][1] = *(const uint32_t*)(sAl + (r0 + 8) * SKP + kb);
                al[mt][2] = *(const uint32_t*)(sAl + r0 * SKP + kb + 8);
                al[mt][3] = *(const uint32_t*)(sAl + (r0 + 8) * SKP + kb + 8);
            }
            #pragma unroll
            for (int nt = 0; nt < 8; nt++) {
                int rn = br + nt * 8;
                bh[nt][0] = *(const uint32_t*)(sBh + rn * SKP + kb);
                bh[nt][1] = *(const uint32_t*)(sBh + rn * SKP + kb + 8);
                bl[nt][0] = *(const uint32_t*)(sBl + rn * SKP + kb);
                bl[nt][1] = *(const uint32_t*)(sBl + rn * SKP + kb + 8);
            }
            #pragma unroll
            for (int mt = 0; mt < 2; mt++)
                #pragma unroll
                for (int nt = 0; nt < 8; nt++) {
                    mma_bf16(c[mt][nt], ah[mt], bh[nt]);
                    mma_bf16(c[mt][nt], ah[mt], bl[nt]);
                    mma_bf16(c[mt][nt], al[mt], bh[nt]);
                }
        }
        __syncthreads();
    }

    // ---- epilogue ----
    #pragma unroll
    for (int mt = 0; mt < 2; mt++) {
        int r0 = bm + warp_m * 32 + mt * 16 + (lane >> 2);
        #pragma unroll
        for (int nt = 0; nt < 8; nt++) {
            int cc = bn + warp_n * 64 + nt * 8 + (lane & 3) * 2;
            size_t b0 = (size_t)r0 * NC + cc;
            size_t b1 = (size_t)(r0 + 8) * NC + cc;
            if (cc + 1 < NC) {
                out[b0] = c[mt][nt][0]; out[b0 + 1] = c[mt][nt][1];
                out[b1] = c[mt][nt][2]; out[b1 + 1] = c[mt][nt][3];
            } else if (cc < NC) {
                out[b0] = c[mt][nt][0];
                out[b1] = c[mt][nt][2];
            }
        }
    }
}

// ---------------- launch ----------------
extern "C" void kernel_launch(void* const* d_in, const int* in_sizes, int n_in,
                              void* d_out, int out_size) {
    const int*   iid     = (const int*)d_in[2];
    const int*   pid     = (const int*)d_in[3];
    const int*   tidp    = (const int*)d_in[4];
    const int*   i_src   = (const int*)d_in[5];
    const int*   i_dst   = (const int*)d_in[6];
    const int*   agg_src = (const int*)d_in[7];
    const int*   agg_dst = (const int*)d_in[8];
    const float* emb     = (const float*)d_in[9];
    const float* pos_emb = (const float*)d_in[10];
    const float* tgt_emb = (const float*)d_in[11];
    const float* p_w     = (const float*)d_in[12];
    const float* q_w     = (const float*)d_in[13];
    float* out = (float*)d_out;

    const int SMEM_BYTES = 2 * STAGE_STRIDE * 2;  // 2 stages * bf16
    static bool attr_set = false;
    if (!attr_set) {
        cudaFuncSetAttribute(k_scores_mma, cudaFuncAttributeMaxDynamicSharedMemorySize, SMEM_BYTES);
        attr_set = true;
    }

    k_zero     <<<(N_ITEM + 255) / 256, 256>>>();
    k_split_emb<<<((size_t)NUM_NODE * DIM + 255) / 256, 256>>>(emb);
    k_hist     <<<(E_INT + 255) / 256, 256>>>(i_dst, agg_dst);
    k_scan     <<<1, 1024>>>(0);
    k_scan     <<<1, 1024>>>(1);
    k_scatter  <<<(E_INT + 255) / 256, 256>>>(i_dst, agg_dst);
    k_attn     <<<N_ITEM / 8, 256>>>(iid, i_src, emb, p_w);
    k_posB     <<<NPOS, 256>>>(pos_emb, q_w);
    k_coef     <<<N_ITEM / CJ, 256>>>(agg_src, pid, agg_dst, tidp, tgt_emb, q_w);
    k_select   <<<N_TGT, 256>>>(agg_src);
    dim3 g((NUM_NODE - 1 + 127) / 128, N_TGT / 128);
    k_scores_mma<<<g, 256, SMEM_BYTES>>>(out);
}

// round 5
// speedup vs baseline: 2.5205x; 1.4810x over previous
#include <cuda_runtime.h>
#include <cuda_fp16.h>
#include <cstdint>
#include <cstddef>

#define N_ITEM 81920
#define E_INT 327680
#define N_TGT 2048
#define NUM_NODE 50000
#define DIM 256
#define NPOS 200
#define ALPHA 0.2f

// ---------------- device scratch (static, no allocation) ----------------
__device__ __align__(16) float g_ft[(size_t)N_ITEM * DIM];
__device__ __align__(16) __half g_ft_hi[(size_t)N_ITEM * DIM];
__device__ __align__(16) __half g_ft_lo[(size_t)N_ITEM * DIM];
__device__ int   g_deg[N_ITEM];
__device__ int   g_rowoff[N_ITEM + 1];
__device__ int   g_cursor[N_ITEM];
__device__ int   g_perm[E_INT];
__device__ int   g_adeg[N_TGT];
__device__ int   g_arowoff[N_TGT + 1];
__device__ int   g_acursor[N_TGT];
__device__ int   g_aperm[N_ITEM];
__device__ __align__(16) float g_B[NPOS * DIM];
__device__ float g_cpart[4][N_ITEM];     // coef partials: [ctaN*2 + warpN][row]
__device__ __align__(16) __half g_emb_hi[(size_t)NUM_NODE * DIM];
__device__ __align__(16) __half g_emb_lo[(size_t)NUM_NODE * DIM];
__device__ __align__(16) __half g_q_hi[DIM * DIM];
__device__ __align__(16) __half g_q_lo[DIM * DIM];
__device__ __align__(16) __half g_sel_hi[N_TGT * DIM];

__device__ __forceinline__ uint32_t smem_to_u32(const void* p) {
    uint32_t a;
    asm("{ .reg .u64 t; cvta.to.shared.u64 t, %1; cvt.u32.u64 %0, t; }" : "=r"(a) : "l"(p));
    return a;
}
__device__ __forceinline__ void cp16(uint32_t daddr, const void* src, uint32_t srcsize) {
    asm volatile("cp.async.cg.shared.global [%0], [%1], 16, %2;"
                 :: "r"(daddr), "l"(src), "r"(srcsize) : "memory");
}
__device__ __forceinline__ void mma_f16(float* c, const uint32_t* a, const uint32_t* b) {
    asm volatile("mma.sync.aligned.m16n8k16.row.col.f32.f16.f16.f32 "
                 "{%0,%1,%2,%3}, {%4,%5,%6,%7}, {%8,%9}, {%0,%1,%2,%3};"
                 : "+f"(c[0]), "+f"(c[1]), "+f"(c[2]), "+f"(c[3])
                 : "r"(a[0]), "r"(a[1]), "r"(a[2]), "r"(a[3]), "r"(b[0]), "r"(b[1]));
}
__device__ __forceinline__ void ldsm4(uint32_t* r, uint32_t addr) {
    asm volatile("ldmatrix.sync.aligned.m8n8.x4.shared.b16 {%0,%1,%2,%3}, [%4];"
                 : "=r"(r[0]), "=r"(r[1]), "=r"(r[2]), "=r"(r[3]) : "r"(addr));
}
// A 16x16 fp16 tile (row-major rows, 80B row stride) -> a-frag {a0,a1,a2,a3}
__device__ __forceinline__ void ldsm_A(uint32_t* r4, uint32_t base, int row0, int kbyte, int lane) {
    int m = lane >> 3, rr = lane & 7;
    uint32_t addr = base + (uint32_t)(row0 + ((m & 1) << 3) + rr) * 80u + kbyte + ((m >> 1) << 4);
    ldsm4(r4, addr);
}
// B: 16 n-rows x 16 k (row-major n rows, 80B stride) -> {b0(nt0),b1(nt0),b0(nt1),b1(nt1)}
__device__ __forceinline__ void ldsm_B(uint32_t* r4, uint32_t base, int n0, int kbyte, int lane) {
    int m = lane >> 3, rr = lane & 7;
    uint32_t addr = base + (uint32_t)(n0 + ((m >> 1) << 3) + rr) * 80u + kbyte + ((m & 1) << 4);
    ldsm4(r4, addr);
}

// ---------------- init ----------------
__global__ void k_zero() {
    int i = blockIdx.x * blockDim.x + threadIdx.x;
    if (i < N_ITEM) g_deg[i] = 0;
    if (i < N_TGT)  g_adeg[i] = 0;
}

// ---------------- fp16 hi/lo splits ----------------
__global__ void k_split_emb(const float* __restrict__ emb) {
    size_t i = (size_t)blockIdx.x * blockDim.x + threadIdx.x;
    if (i >= (size_t)NUM_NODE * DIM) return;
    float x = emb[i];
    __half h = __float2half(x);
    g_emb_hi[i] = h;
    g_emb_lo[i] = __float2half(x - __half2float(h));
}
__global__ void k_split_q(const float* __restrict__ q_w) {
    int i = blockIdx.x * blockDim.x + threadIdx.x;
    if (i >= DIM * DIM) return;
    int d = i >> 8, k = i & 255;
    float x = q_w[(size_t)d * (2 * DIM) + k];
    __half h = __float2half(x);
    g_q_hi[i] = h;
    g_q_lo[i] = __float2half(x - __half2float(h));
}

// ---------------- histograms / scan / scatter ----------------
__global__ void k_hist(const int* __restrict__ i_dst, const int* __restrict__ agg_dst) {
    int i = blockIdx.x * blockDim.x + threadIdx.x;
    if (i < E_INT)  atomicAdd(&g_deg[i_dst[i]], 1);
    if (i < N_ITEM) atomicAdd(&g_adeg[agg_dst[i]], 1);
}
__global__ void k_scan(int which) {
    const int* deg; int* rowoff; int* cursor; int n;
    if (which == 0) { deg = g_deg;  rowoff = g_rowoff;  cursor = g_cursor;  n = N_ITEM; }
    else            { deg = g_adeg; rowoff = g_arowoff; cursor = g_acursor; n = N_TGT;  }
    __shared__ int s[1024];
    int t = threadIdx.x;
    int per = (n + 1023) / 1024;
    int st = t * per, en = st + per; if (en > n) en = n;
    int sum = 0;
    for (int i = st; i < en; i++) sum += deg[i];
    s[t] = sum;
    __syncthreads();
    for (int off = 1; off < 1024; off <<= 1) {
        int v = (t >= off) ? s[t - off] : 0;
        __syncthreads();
        if (t >= off) s[t] += v;
        __syncthreads();
    }
    int run = (t == 0) ? 0 : s[t - 1];
    for (int i = st; i < en; i++) { rowoff[i] = run; cursor[i] = run; run += deg[i]; }
    if (t == 1023) rowoff[n] = s[1023];
}
__global__ void k_scatter(const int* __restrict__ i_dst, const int* __restrict__ agg_dst) {
    int i = blockIdx.x * blockDim.x + threadIdx.x;
    if (i < E_INT) { int d = i_dst[i]; g_perm[atomicAdd(&g_cursor[d], 1)] = i; }
    if (i < N_ITEM) { int d = agg_dst[i]; g_aperm[atomicAdd(&g_acursor[d], 1)] = i; }
}

// ---------------- single-pass attention (softmax shift-invariant; |logit|<0.1) ----------------
__global__ void __launch_bounds__(256) k_attn(const int* __restrict__ iid,
                                              const int* __restrict__ i_src,
                                              const float* __restrict__ emb,
                                              const float* __restrict__ p_w) {
    int gw   = (blockIdx.x * blockDim.x + threadIdx.x) >> 5;
    int lane = threadIdx.x & 31;
    if (gw >= N_ITEM) return;
    int v = gw;
    const float4* embv = (const float4*)emb;
    int c0 = lane * 2;
    size_t rv = (size_t)iid[v] * (DIM / 4);
    float4 hd0 = embv[rv + c0];
    float4 hd1 = embv[rv + c0 + 1];
    float4 pw0 = ((const float4*)p_w)[c0];
    float4 pw1 = ((const float4*)p_w)[c0 + 1];
    int rs = g_rowoff[v], re = g_rowoff[v + 1];

    float den = 0.f;
    float4 a0 = make_float4(0.f,0.f,0.f,0.f), a1 = make_float4(0.f,0.f,0.f,0.f);
    for (int idx = rs; idx < re; idx++) {
        int e = g_perm[idx];
        size_t ru = (size_t)iid[i_src[e]] * (DIM / 4);
        float4 hs0 = embv[ru + c0];
        float4 hs1 = embv[ru + c0 + 1];
        float p = hs0.x*hd0.x*pw0.x + hs0.y*hd0.y*pw0.y + hs0.z*hd0.z*pw0.z + hs0.w*hd0.w*pw0.w
                + hs1.x*hd1.x*pw1.x + hs1.y*hd1.y*pw1.y + hs1.z*hd1.z*pw1.z + hs1.w*hd1.w*pw1.w;
        #pragma unroll
        for (int o = 16; o; o >>= 1) p += __shfl_xor_sync(0xffffffffu, p, o);
        p = (p >= 0.f) ? p : ALPHA * p;
        float ex = expf(p);
        den += ex;
        a0.x += ex*hs0.x; a0.y += ex*hs0.y; a0.z += ex*hs0.z; a0.w += ex*hs0.w;
        a1.x += ex*hs1.x; a1.y += ex*hs1.y; a1.z += ex*hs1.z; a1.w += ex*hs1.w;
    }
    float inv = 1.f / fmaxf(den, 1e-12f);
    float o[8] = { a0.x*inv, a0.y*inv, a0.z*inv, a0.w*inv,
                   a1.x*inv, a1.y*inv, a1.z*inv, a1.w*inv };
    ((float4*)g_ft)[(size_t)v*(DIM/4) + c0]     = make_float4(o[0], o[1], o[2], o[3]);
    ((float4*)g_ft)[(size_t)v*(DIM/4) + c0 + 1] = make_float4(o[4], o[5], o[6], o[7]);
    union { __half h[8]; uint4 u; } ph, pl;
    #pragma unroll
    for (int q = 0; q < 8; q++) {
        __half h = __float2half(o[q]);
        ph.h[q] = h;
        pl.h[q] = __float2half(o[q] - __half2float(h));
    }
    ((uint4*)g_ft_hi)[(size_t)v * 32 + lane] = ph.u;
    ((uint4*)g_ft_lo)[(size_t)v * 32 + lane] = pl.u;
}

// ---------------- B = pos_emb @ q_w[:,256:].T ----------------
__global__ void k_posB(const float* __restrict__ pos_emb, const float* __restrict__ q_w) {
    int p = blockIdx.x, d = threadIdx.x;
    __shared__ float sp[DIM];
    sp[d] = pos_emb[p * DIM + d];
    __syncthreads();
    const float4* q4 = (const float4*)(q_w + (size_t)d * (2 * DIM) + DIM);
    float acc = 0.f;
    #pragma unroll 8
    for (int k = 0; k < DIM / 4; k++) {
        float4 q = q4[k];
        acc += sp[4*k]*q.x + sp[4*k+1]*q.y + sp[4*k+2]*q.z + sp[4*k+3]*q.w;
    }
    g_B[p * DIM + d] = acc;
}

// ================= k_coef via mma (3-term fp16 split) =================
// Y[128j x 128d] = ft[sj] @ q1^T ; coef partial = sum_d tanh(Y + Bpos)*ht
#define SKPH 40
#define ASZ (128 * SKPH * 2)      // 10240 B per array per stage
#define STG_C (4 * ASZ)           // 40960
#define OFF_SJ   (2 * STG_C)      // 81920
#define OFF_SPID (OFF_SJ + 512)
#define OFF_ST   (OFF_SPID + 512)
#define OFF_BPOS (OFF_ST + 512)   // 83456
#define SMEM_C   (OFF_BPOS + 128 * 132 * 4)   // 151040

__global__ void __launch_bounds__(256) k_coef_mma(const int* __restrict__ agg_src,
                                                  const int* __restrict__ pid,
                                                  const int* __restrict__ agg_dst,
                                                  const int* __restrict__ tid,
                                                  const float* __restrict__ tgt_emb) {
    extern __shared__ char smc[];
    uint32_t sb = smem_to_u32(smc);
    int* sj   = (int*)(smc + OFF_SJ);
    int* spid = (int*)(smc + OFF_SPID);
    int* stt  = (int*)(smc + OFF_ST);
    float* sBpos = (float*)(smc + OFF_BPOS);

    int t = threadIdx.x, lane = t & 31, wid = t >> 5;
    int wm = wid & 3, wn = wid >> 2;
    int bn = blockIdx.x * 128;               // d-tile (0 or 128)
    int j0 = blockIdx.y * 128;

    if (t < 128) {
        sj[t]   = agg_src[j0 + t];
        spid[t] = pid[j0 + t];
        stt[t]  = tid[agg_dst[j0 + t]];
    }
    __syncthreads();

    const uint4* Fh4 = (const uint4*)g_ft_hi;
    const uint4* Fl4 = (const uint4*)g_ft_lo;
    const uint4* Qh4 = (const uint4*)g_q_hi;
    const uint4* Ql4 = (const uint4*)g_q_lo;

    auto prefetch = [&](int stage, int kc) {
        for (int i = t; i < 2048; i += 256) {
            int arr = i >> 9;               // 0 Ah,1 Al,2 Bh,3 Bl
            int r   = (i >> 2) & 127;
            int v   = i & 3;
            uint32_t daddr = sb + stage * STG_C + arr * ASZ + r * (SKPH*2) + v * 16;
            if (arr < 2) {
                size_t off = (size_t)sj[r] * 32 + kc * 4 + v;
                cp16(daddr, (arr == 0 ? Fh4 : Fl4) + off, 16);
            } else {
                size_t off = (size_t)(bn + r) * 32 + kc * 4 + v;
                cp16(daddr, (arr == 2 ? Qh4 : Ql4) + off, 16);
            }
        }
        asm volatile("cp.async.commit_group;" ::: "memory");
    };

    float c[2][8][4];
    #pragma unroll
    for (int mt = 0; mt < 2; mt++)
        #pragma unroll
        for (int nt = 0; nt < 8; nt++)
            #pragma unroll
            for (int q = 0; q < 4; q++) c[mt][nt][q] = 0.f;

    prefetch(0, 0);
    for (int kc = 0; kc < 8; kc++) {
        int s = kc & 1;
        if (kc + 1 < 8) {
            prefetch(1 - s, kc + 1);
            asm volatile("cp.async.wait_group 1;" ::: "memory");
        } else {
            asm volatile("cp.async.wait_group 0;" ::: "memory");
        }
        __syncthreads();
        uint32_t sAh = sb + s * STG_C;
        uint32_t sAl = sAh + ASZ;
        uint32_t sBh = sAl + ASZ;
        uint32_t sBl = sBh + ASZ;
        #pragma unroll
        for (int ks = 0; ks < 2; ks++) {
            int kbyte = ks * 32;
            uint32_t ah[2][4], al[2][4], bh[4][4], bl[4][4];
            ldsm_A(ah[0], sAh, wm*32,      kbyte, lane);
            ldsm_A(ah[1], sAh, wm*32 + 16, kbyte, lane);
            ldsm_A(al[0], sAl, wm*32,      kbyte, lane);
            ldsm_A(al[1], sAl, wm*32 + 16, kbyte, lane);
            #pragma unroll
            for (int g = 0; g < 4; g++) {
                ldsm_B(bh[g], sBh, wn*64 + g*16, kbyte, lane);
                ldsm_B(bl[g], sBl, wn*64 + g*16, kbyte, lane);
            }
            #pragma unroll
            for (int mt = 0; mt < 2; mt++)
                #pragma unroll
                for (int nt = 0; nt < 8; nt++) {
                    const uint32_t* ph = &bh[nt >> 1][(nt & 1) * 2];
                    const uint32_t* pl2 = &bl[nt >> 1][(nt & 1) * 2];
                    mma_f16(c[mt][nt], ah[mt], ph);
                    mma_f16(c[mt][nt], ah[mt], pl2);
                    mma_f16(c[mt][nt], al[mt], ph);
                }
        }
        __syncthreads();
    }

    // stage Bpos rows into smem (coalesced)
    for (int i = t; i < 128 * 32; i += 256) {
        int r = i >> 5, v = i & 31;
        float4 val = ((const float4*)g_B)[(size_t)spid[r] * 64 + (bn >> 2) + v];
        *(float4*)&sBpos[r * 132 + v * 4] = val;
    }
    __syncthreads();

    // epilogue: tanh + ht dot, reduce over this warp's 64 cols, store partial slot
    int slot = blockIdx.x * 2 + wn;
    #pragma unroll
    for (int mt = 0; mt < 2; mt++)
        #pragma unroll
        for (int half = 0; half < 2; half++) {
            int rl = wm*32 + mt*16 + half*8 + (lane >> 2);
            const float* htr = tgt_emb + (size_t)stt[rl] * DIM + bn;
            float p = 0.f;
            #pragma unroll
            for (int nt = 0; nt < 8; nt++) {
                int cl = wn*64 + nt*8 + (lane & 3)*2;
                float y0 = c[mt][nt][half*2 + 0] + sBpos[rl*132 + cl];
                float y1 = c[mt][nt][half*2 + 1] + sBpos[rl*132 + cl + 1];
                p += tanhf(y0) * htr[cl] + tanhf(y1) * htr[cl + 1];
            }
            p += __shfl_xor_sync(0xffffffffu, p, 1);
            p += __shfl_xor_sync(0xffffffffu, p, 2);
            if ((lane & 3) == 0) g_cpart[slot][j0 + rl] = p;
        }
}

// ---------------- select (sums 4 coef partials deterministically) ----------------
__global__ void k_select(const int* __restrict__ agg_src) {
    int tgt = blockIdx.x;
    int d = threadIdx.x;
    float acc = 0.f;
    int rs = g_arowoff[tgt], re = g_arowoff[tgt + 1];
    for (int idx = rs; idx < re; idx++) {
        int j = g_aperm[idx];
        float coef = (g_cpart[0][j] + g_cpart[1][j]) + (g_cpart[2][j] + g_cpart[3][j]);
        acc += coef * g_ft[(size_t)agg_src[j] * DIM + d];
    }
    g_sel_hi[tgt * DIM + d] = __float2half(acc);
}

// ================= scores: fp16 2-term (Ah*Bh + Ah*Bl), ldmatrix =================
#define STG_S (3 * ASZ)           // 30720
#define SMEM_S (2 * STG_S)        // 61440

__global__ void __launch_bounds__(256) k_scores_mma(float* __restrict__ out) {
    extern __shared__ char sms[];
    uint32_t sb = smem_to_u32(sms);
    int t = threadIdx.x, lane = t & 31, wid = t >> 5;
    int wm = wid & 3, wn = wid >> 2;
    int bm = blockIdx.y * 128;
    int bn = blockIdx.x * 128;
    const int NC = NUM_NODE - 1;

    const uint4* Ah4 = (const uint4*)g_sel_hi;
    const uint4* Bh4 = (const uint4*)g_emb_hi;
    const uint4* Bl4 = (const uint4*)g_emb_lo;

    auto prefetch = [&](int stage, int kc) {
        for (int i = t; i < 1536; i += 256) {
            int arr = i >> 9;               // 0 Ah, 1 Bh, 2 Bl
            int r   = (i >> 2) & 127;
            int v   = i & 3;
            uint32_t daddr = sb + stage * STG_S + arr * ASZ + r * (SKPH*2) + v * 16;
            if (arr == 0) {
                cp16(daddr, Ah4 + ((size_t)(bm + r) * 32 + kc * 4 + v), 16);
            } else {
                int er = bn + r + 1;
                size_t off = (size_t)(er < NUM_NODE ? er : 0) * 32 + kc * 4 + v;
                cp16(daddr, (arr == 1 ? Bh4 : Bl4) + off, er < NUM_NODE ? 16u : 0u);
            }
        }
        asm volatile("cp.async.commit_group;" ::: "memory");
    };

    float c[2][8][4];
    #pragma unroll
    for (int mt = 0; mt < 2; mt++)
        #pragma unroll
        for (int nt = 0; nt < 8; nt++)
            #pragma unroll
            for (int q = 0; q < 4; q++) c[mt][nt][q] = 0.f;

    prefetch(0, 0);
    for (int kc = 0; kc < 8; kc++) {
        int s = kc & 1;
        if (kc + 1 < 8) {
            prefetch(1 - s, kc + 1);
            asm volatile("cp.async.wait_group 1;" ::: "memory");
        } else {
            asm volatile("cp.async.wait_group 0;" ::: "memory");
        }
        __syncthreads();
        uint32_t sAh = sb + s * STG_S;
        uint32_t sBh = sAh + ASZ;
        uint32_t sBl = sBh + ASZ;
        #pragma unroll
        for (int ks = 0; ks < 2; ks++) {
            int kbyte = ks * 32;
            uint32_t ah[2][4], bh[4][4], bl[4][4];
            ldsm_A(ah[0], sAh, wm*32,      kbyte, lane);
            ldsm_A(ah[1], sAh, wm*32 + 16, kbyte, lane);
            #pragma unroll
            for (int g = 0; g < 4; g++) {
                ldsm_B(bh[g], sBh, wn*64 + g*16, kbyte, lane);
                ldsm_B(bl[g], sBl, wn*64 + g*16, kbyte, lane);
            }
            #pragma unroll
            for (int mt = 0; mt < 2; mt++)
                #pragma unroll
                for (int nt = 0; nt < 8; nt++) {
                    mma_f16(c[mt][nt], ah[mt], &bh[nt >> 1][(nt & 1) * 2]);
                    mma_f16(c[mt][nt], ah[mt], &bl[nt >> 1][(nt & 1) * 2]);
                }
        }
        __syncthreads();
    }

    #pragma unroll
    for (int mt = 0; mt < 2; mt++) {
        int r0 = bm + wm * 32 + mt * 16 + (lane >> 2);
        #pragma unroll
        for (int nt = 0; nt < 8; nt++) {
            int cc = bn + wn * 64 + nt * 8 + (lane & 3) * 2;
            size_t b0 = (size_t)r0 * NC + cc;
            size_t b1 = (size_t)(r0 + 8) * NC + cc;
            if (cc + 1 < NC) {
                out[b0] = c[mt][nt][0]; out[b0 + 1] = c[mt][nt][1];
                out[b1] = c[mt][nt][2]; out[b1 + 1] = c[mt][nt][3];
            } else if (cc < NC) {
                out[b0] = c[mt][nt][0];
                out[b1] = c[mt][nt][2];
            }
        }
    }
}

// ---------------- launch ----------------
extern "C" void kernel_launch(void* const* d_in, const int* in_sizes, int n_in,
                              void* d_out, int out_size) {
    const int*   iid     = (const int*)d_in[2];
    const int*   pid     = (const int*)d_in[3];
    const int*   tidp    = (const int*)d_in[4];
    const int*   i_src   = (const int*)d_in[5];
    const int*   i_dst   = (const int*)d_in[6];
    const int*   agg_src = (const int*)d_in[7];
    const int*   agg_dst = (const int*)d_in[8];
    const float* emb     = (const float*)d_in[9];
    const float* pos_emb = (const float*)d_in[10];
    const float* tgt_emb = (const float*)d_in[11];
    const float* p_w     = (const float*)d_in[12];
    const float* q_w     = (const float*)d_in[13];
    float* out = (float*)d_out;

    static bool attr_set = false;
    if (!attr_set) {
        cudaFuncSetAttribute(k_scores_mma, cudaFuncAttributeMaxDynamicSharedMemorySize, SMEM_S);
        cudaFuncSetAttribute(k_coef_mma,   cudaFuncAttributeMaxDynamicSharedMemorySize, SMEM_C);
        attr_set = true;
    }

    k_zero     <<<(N_ITEM + 255) / 256, 256>>>();
    k_split_emb<<<((size_t)NUM_NODE * DIM + 255) / 256, 256>>>(emb);
    k_split_q  <<<(DIM * DIM + 255) / 256, 256>>>(q_w);
    k_hist     <<<(E_INT + 255) / 256, 256>>>(i_dst, agg_dst);
    k_scan     <<<1, 1024>>>(0);
    k_scan     <<<1, 1024>>>(1);
    k_scatter  <<<(E_INT + 255) / 256, 256>>>(i_dst, agg_dst);
    k_attn     <<<N_ITEM / 8, 256>>>(iid, i_src, emb, p_w);
    k_posB     <<<NPOS, 256>>>(pos_emb, q_w);
    dim3 gc(2, N_ITEM / 128);
    k_coef_mma <<<gc, 256, SMEM_C>>>(agg_src, pid, agg_dst, tidp, tgt_emb);
    k_select   <<<N_TGT, 256>>>(agg_src);
    dim3 gs((NUM_NODE - 1 + 127) / 128, N_TGT / 128);
    k_scores_mma<<<gs, 256, SMEM_S>>>(out);
}

// round 6
// speedup vs baseline: 2.8177x; 1.1179x over previous
#include <cuda_runtime.h>
#include <cuda_fp16.h>
#include <cstdint>
#include <cstddef>

#define N_ITEM 81920
#define E_INT 327680
#define N_TGT 2048
#define NUM_NODE 50000
#define DIM 256
#define NPOS 200
#define ALPHA 0.2f

// ---------------- device scratch (static, no allocation) ----------------
__device__ __align__(16) float g_ft[(size_t)N_ITEM * DIM];
__device__ __align__(16) __half g_ft_hi[(size_t)N_ITEM * DIM];
__device__ __align__(16) __half g_ft_lo[(size_t)N_ITEM * DIM];
__device__ int   g_deg[N_ITEM];
__device__ int   g_rowoff[N_ITEM + 1];
__device__ int   g_cursor[N_ITEM];
__device__ int   g_perm[E_INT];
__device__ int   g_adeg[N_TGT];
__device__ int   g_arowoff[N_TGT + 1];
__device__ int   g_acursor[N_TGT];
__device__ int   g_aperm[N_ITEM];
__device__ __align__(16) float g_B[NPOS * DIM];
__device__ float g_cpart[4][N_ITEM];     // coef partials: [ctaN*2 + warpN][row]
__device__ __align__(16) __half g_emb_hi[(size_t)NUM_NODE * DIM];
__device__ __align__(16) __half g_q_hi[DIM * DIM];
__device__ __align__(16) __half g_q_lo[DIM * DIM];
__device__ __align__(16) __half g_sel_hi[N_TGT * DIM];

__device__ __forceinline__ uint32_t smem_to_u32(const void* p) {
    uint32_t a;
    asm("{ .reg .u64 t; cvta.to.shared.u64 t, %1; cvt.u32.u64 %0, t; }" : "=r"(a) : "l"(p));
    return a;
}
__device__ __forceinline__ void cp16(uint32_t daddr, const void* src, uint32_t srcsize) {
    asm volatile("cp.async.cg.shared.global [%0], [%1], 16, %2;"
                 :: "r"(daddr), "l"(src), "r"(srcsize) : "memory");
}
__device__ __forceinline__ void mma_f16(float* c, const uint32_t* a, const uint32_t* b) {
    asm volatile("mma.sync.aligned.m16n8k16.row.col.f32.f16.f16.f32 "
                 "{%0,%1,%2,%3}, {%4,%5,%6,%7}, {%8,%9}, {%0,%1,%2,%3};"
                 : "+f"(c[0]), "+f"(c[1]), "+f"(c[2]), "+f"(c[3])
                 : "r"(a[0]), "r"(a[1]), "r"(a[2]), "r"(a[3]), "r"(b[0]), "r"(b[1]));
}
__device__ __forceinline__ void ldsm4(uint32_t* r, uint32_t addr) {
    asm volatile("ldmatrix.sync.aligned.m8n8.x4.shared.b16 {%0,%1,%2,%3}, [%4];"
                 : "=r"(r[0]), "=r"(r[1]), "=r"(r[2]), "=r"(r[3]) : "r"(addr));
}
// A 16x16 fp16 tile (row-major rows, 80B row stride) -> a-frag {a0,a1,a2,a3}
__device__ __forceinline__ void ldsm_A(uint32_t* r4, uint32_t base, int row0, int kbyte, int lane) {
    int m = lane >> 3, rr = lane & 7;
    uint32_t addr = base + (uint32_t)(row0 + ((m & 1) << 3) + rr) * 80u + kbyte + ((m >> 1) << 4);
    ldsm4(r4, addr);
}
// B: 16 n-rows x 16 k (row-major n rows, 80B stride) -> {b0(nt0),b1(nt0),b0(nt1),b1(nt1)}
__device__ __forceinline__ void ldsm_B(uint32_t* r4, uint32_t base, int n0, int kbyte, int lane) {
    int m = lane >> 3, rr = lane & 7;
    uint32_t addr = base + (uint32_t)(n0 + ((m >> 1) << 3) + rr) * 80u + kbyte + ((m & 1) << 4);
    ldsm4(r4, addr);
}

// ---------------- init ----------------
__global__ void k_zero() {
    int i = blockIdx.x * blockDim.x + threadIdx.x;
    if (i < N_ITEM) g_deg[i] = 0;
    if (i < N_TGT)  g_adeg[i] = 0;
}

// ---------------- fp16 splits ----------------
__global__ void k_split_emb(const float* __restrict__ emb) {
    size_t i = (size_t)blockIdx.x * blockDim.x + threadIdx.x;
    if (i >= (size_t)NUM_NODE * DIM) return;
    g_emb_hi[i] = __float2half(emb[i]);
}
__global__ void k_split_q(const float* __restrict__ q_w) {
    int i = blockIdx.x * blockDim.x + threadIdx.x;
    if (i >= DIM * DIM) return;
    int d = i >> 8, k = i & 255;
    float x = q_w[(size_t)d * (2 * DIM) + k];
    __half h = __float2half(x);
    g_q_hi[i] = h;
    g_q_lo[i] = __float2half(x - __half2float(h));
}

// ---------------- histograms / scan / scatter ----------------
__global__ void k_hist(const int* __restrict__ i_dst, const int* __restrict__ agg_dst) {
    int i = blockIdx.x * blockDim.x + threadIdx.x;
    if (i < E_INT)  atomicAdd(&g_deg[i_dst[i]], 1);
    if (i < N_ITEM) atomicAdd(&g_adeg[agg_dst[i]], 1);
}
__global__ void k_scan(int which) {
    const int* deg; int* rowoff; int* cursor; int n;
    if (which == 0) { deg = g_deg;  rowoff = g_rowoff;  cursor = g_cursor;  n = N_ITEM; }
    else            { deg = g_adeg; rowoff = g_arowoff; cursor = g_acursor; n = N_TGT;  }
    __shared__ int s[1024];
    int t = threadIdx.x;
    int per = (n + 1023) / 1024;
    int st = t * per, en = st + per; if (en > n) en = n;
    int sum = 0;
    for (int i = st; i < en; i++) sum += deg[i];
    s[t] = sum;
    __syncthreads();
    for (int off = 1; off < 1024; off <<= 1) {
        int v = (t >= off) ? s[t - off] : 0;
        __syncthreads();
        if (t >= off) s[t] += v;
        __syncthreads();
    }
    int run = (t == 0) ? 0 : s[t - 1];
    for (int i = st; i < en; i++) { rowoff[i] = run; cursor[i] = run; run += deg[i]; }
    if (t == 1023) rowoff[n] = s[1023];
}
__global__ void k_scatter(const int* __restrict__ i_dst, const int* __restrict__ agg_dst) {
    int i = blockIdx.x * blockDim.x + threadIdx.x;
    if (i < E_INT) { int d = i_dst[i]; g_perm[atomicAdd(&g_cursor[d], 1)] = i; }
    if (i < N_ITEM) { int d = agg_dst[i]; g_aperm[atomicAdd(&g_acursor[d], 1)] = i; }
}

// ---------------- single-pass attention (softmax shift-invariant; |logit|<0.1) ----------------
__global__ void __launch_bounds__(256) k_attn(const int* __restrict__ iid,
                                              const int* __restrict__ i_src,
                                              const float* __restrict__ emb,
                                              const float* __restrict__ p_w) {
    int gw   = (blockIdx.x * blockDim.x + threadIdx.x) >> 5;
    int lane = threadIdx.x & 31;
    if (gw >= N_ITEM) return;
    int v = gw;
    const float4* embv = (const float4*)emb;
    int c0 = lane * 2;
    size_t rv = (size_t)iid[v] * (DIM / 4);
    float4 hd0 = embv[rv + c0];
    float4 hd1 = embv[rv + c0 + 1];
    float4 pw0 = ((const float4*)p_w)[c0];
    float4 pw1 = ((const float4*)p_w)[c0 + 1];
    int rs = g_rowoff[v], re = g_rowoff[v + 1];

    float den = 0.f;
    float4 a0 = make_float4(0.f,0.f,0.f,0.f), a1 = make_float4(0.f,0.f,0.f,0.f);
    for (int idx = rs; idx < re; idx++) {
        int e = g_perm[idx];
        size_t ru = (size_t)iid[i_src[e]] * (DIM / 4);
        float4 hs0 = embv[ru + c0];
        float4 hs1 = embv[ru + c0 + 1];
        float p = hs0.x*hd0.x*pw0.x + hs0.y*hd0.y*pw0.y + hs0.z*hd0.z*pw0.z + hs0.w*hd0.w*pw0.w
                + hs1.x*hd1.x*pw1.x + hs1.y*hd1.y*pw1.y + hs1.z*hd1.z*pw1.z + hs1.w*hd1.w*pw1.w;
        #pragma unroll
        for (int o = 16; o; o >>= 1) p += __shfl_xor_sync(0xffffffffu, p, o);
        p = (p >= 0.f) ? p : ALPHA * p;
        float ex = expf(p);
        den += ex;
        a0.x += ex*hs0.x; a0.y += ex*hs0.y; a0.z += ex*hs0.z; a0.w += ex*hs0.w;
        a1.x += ex*hs1.x; a1.y += ex*hs1.y; a1.z += ex*hs1.z; a1.w += ex*hs1.w;
    }
    float inv = 1.f / fmaxf(den, 1e-12f);
    float o[8] = { a0.x*inv, a0.y*inv, a0.z*inv, a0.w*inv,
                   a1.x*inv, a1.y*inv, a1.z*inv, a1.w*inv };
    ((float4*)g_ft)[(size_t)v*(DIM/4) + c0]     = make_float4(o[0], o[1], o[2], o[3]);
    ((float4*)g_ft)[(size_t)v*(DIM/4) + c0 + 1] = make_float4(o[4], o[5], o[6], o[7]);
    union { __half h[8]; uint4 u; } ph, pl;
    #pragma unroll
    for (int q = 0; q < 8; q++) {
        __half h = __float2half(o[q]);
        ph.h[q] = h;
        pl.h[q] = __float2half(o[q] - __half2float(h));
    }
    ((uint4*)g_ft_hi)[(size_t)v * 32 + lane] = ph.u;
    ((uint4*)g_ft_lo)[(size_t)v * 32 + lane] = pl.u;
}

// ---------------- B = pos_emb @ q_w[:,256:].T ----------------
__global__ void k_posB(const float* __restrict__ pos_emb, const float* __restrict__ q_w) {
    int p = blockIdx.x, d = threadIdx.x;
    __shared__ float sp[DIM];
    sp[d] = pos_emb[p * DIM + d];
    __syncthreads();
    const float4* q4 = (const float4*)(q_w + (size_t)d * (2 * DIM) + DIM);
    float acc = 0.f;
    #pragma unroll 8
    for (int k = 0; k < DIM / 4; k++) {
        float4 q = q4[k];
        acc += sp[4*k]*q.x + sp[4*k+1]*q.y + sp[4*k+2]*q.z + sp[4*k+3]*q.w;
    }
    g_B[p * DIM + d] = acc;
}

// ================= k_coef via mma (3-term fp16 split) =================
#define SKPH 40
#define ASZ (128 * SKPH * 2)      // 10240 B per array per stage
#define STG_C (4 * ASZ)           // 40960
#define OFF_SJ   (2 * STG_C)      // 81920
#define OFF_SPID (OFF_SJ + 512)
#define OFF_ST   (OFF_SPID + 512)
#define OFF_BPOS (OFF_ST + 512)   // 83456
#define SMEM_C   (OFF_BPOS + 128 * 132 * 4)   // 151040

__global__ void __launch_bounds__(256) k_coef_mma(const int* __restrict__ agg_src,
                                                  const int* __restrict__ pid,
                                                  const int* __restrict__ agg_dst,
                                                  const int* __restrict__ tid,
                                                  const float* __restrict__ tgt_emb) {
    extern __shared__ char smc[];
    uint32_t sb = smem_to_u32(smc);
    int* sj   = (int*)(smc + OFF_SJ);
    int* spid = (int*)(smc + OFF_SPID);
    int* stt  = (int*)(smc + OFF_ST);
    float* sBpos = (float*)(smc + OFF_BPOS);

    int t = threadIdx.x, lane = t & 31, wid = t >> 5;
    int wm = wid & 3, wn = wid >> 2;
    int bn = blockIdx.x * 128;               // d-tile (0 or 128)
    int j0 = blockIdx.y * 128;

    if (t < 128) {
        sj[t]   = agg_src[j0 + t];
        spid[t] = pid[j0 + t];
        stt[t]  = tid[agg_dst[j0 + t]];
    }
    __syncthreads();

    const uint4* Fh4 = (const uint4*)g_ft_hi;
    const uint4* Fl4 = (const uint4*)g_ft_lo;
    const uint4* Qh4 = (const uint4*)g_q_hi;
    const uint4* Ql4 = (const uint4*)g_q_lo;

    auto prefetch = [&](int stage, int kc) {
        for (int i = t; i < 2048; i += 256) {
            int arr = i >> 9;               // 0 Ah,1 Al,2 Bh,3 Bl
            int r   = (i >> 2) & 127;
            int v   = i & 3;
            uint32_t daddr = sb + stage * STG_C + arr * ASZ + r * (SKPH*2) + v * 16;
            if (arr < 2) {
                size_t off = (size_t)sj[r] * 32 + kc * 4 + v;
                cp16(daddr, (arr == 0 ? Fh4 : Fl4) + off, 16);
            } else {
                size_t off = (size_t)(bn + r) * 32 + kc * 4 + v;
                cp16(daddr, (arr == 2 ? Qh4 : Ql4) + off, 16);
            }
        }
        asm volatile("cp.async.commit_group;" ::: "memory");
    };

    float c[2][8][4];
    #pragma unroll
    for (int mt = 0; mt < 2; mt++)
        #pragma unroll
        for (int nt = 0; nt < 8; nt++)
            #pragma unroll
            for (int q = 0; q < 4; q++) c[mt][nt][q] = 0.f;

    prefetch(0, 0);
    for (int kc = 0; kc < 8; kc++) {
        int s = kc & 1;
        if (kc + 1 < 8) {
            prefetch(1 - s, kc + 1);
            asm volatile("cp.async.wait_group 1;" ::: "memory");
        } else {
            asm volatile("cp.async.wait_group 0;" ::: "memory");
        }
        __syncthreads();
        uint32_t sAh = sb + s * STG_C;
        uint32_t sAl = sAh + ASZ;
        uint32_t sBh = sAl + ASZ;
        uint32_t sBl = sBh + ASZ;
        #pragma unroll
        for (int ks = 0; ks < 2; ks++) {
            int kbyte = ks * 32;
            uint32_t ah[2][4], al[2][4], bh[4][4], bl[4][4];
            ldsm_A(ah[0], sAh, wm*32,      kbyte, lane);
            ldsm_A(ah[1], sAh, wm*32 + 16, kbyte, lane);
            ldsm_A(al[0], sAl, wm*32,      kbyte, lane);
            ldsm_A(al[1], sAl, wm*32 + 16, kbyte, lane);
            #pragma unroll
            for (int g = 0; g < 4; g++) {
                ldsm_B(bh[g], sBh, wn*64 + g*16, kbyte, lane);
                ldsm_B(bl[g], sBl, wn*64 + g*16, kbyte, lane);
            }
            #pragma unroll
            for (int mt = 0; mt < 2; mt++)
                #pragma unroll
                for (int nt = 0; nt < 8; nt++) {
                    const uint32_t* ph = &bh[nt >> 1][(nt & 1) * 2];
                    const uint32_t* pl2 = &bl[nt >> 1][(nt & 1) * 2];
                    mma_f16(c[mt][nt], ah[mt], ph);
                    mma_f16(c[mt][nt], ah[mt], pl2);
                    mma_f16(c[mt][nt], al[mt], ph);
                }
        }
        __syncthreads();
    }

    for (int i = t; i < 128 * 32; i += 256) {
        int r = i >> 5, v = i & 31;
        float4 val = ((const float4*)g_B)[(size_t)spid[r] * 64 + (bn >> 2) + v];
        *(float4*)&sBpos[r * 132 + v * 4] = val;
    }
    __syncthreads();

    int slot = blockIdx.x * 2 + wn;
    #pragma unroll
    for (int mt = 0; mt < 2; mt++)
        #pragma unroll
        for (int half = 0; half < 2; half++) {
            int rl = wm*32 + mt*16 + half*8 + (lane >> 2);
            const float* htr = tgt_emb + (size_t)stt[rl] * DIM + bn;
            float p = 0.f;
            #pragma unroll
            for (int nt = 0; nt < 8; nt++) {
                int cl = wn*64 + nt*8 + (lane & 3)*2;
                float y0 = c[mt][nt][half*2 + 0] + sBpos[rl*132 + cl];
                float y1 = c[mt][nt][half*2 + 1] + sBpos[rl*132 + cl + 1];
                p += tanhf(y0) * htr[cl] + tanhf(y1) * htr[cl + 1];
            }
            p += __shfl_xor_sync(0xffffffffu, p, 1);
            p += __shfl_xor_sync(0xffffffffu, p, 2);
            if ((lane & 3) == 0) g_cpart[slot][j0 + rl] = p;
        }
}

// ---------------- select (sums 4 coef partials deterministically) ----------------
__global__ void k_select(const int* __restrict__ agg_src) {
    int tgt = blockIdx.x;
    int d = threadIdx.x;
    float acc = 0.f;
    int rs = g_arowoff[tgt], re = g_arowoff[tgt + 1];
    for (int idx = rs; idx < re; idx++) {
        int j = g_aperm[idx];
        float coef = (g_cpart[0][j] + g_cpart[1][j]) + (g_cpart[2][j] + g_cpart[3][j]);
        acc += coef * g_ft[(size_t)agg_src[j] * DIM + d];
    }
    g_sel_hi[tgt * DIM + d] = __float2half(acc);
}

// ================= scores: single-term fp16 (Ah*Bh), ldmatrix =================
#define STG_S (2 * ASZ)           // 20480
#define SMEM_S (2 * STG_S)        // 40960

__global__ void __launch_bounds__(256) k_scores_mma(float* __restrict__ out) {
    extern __shared__ char sms[];
    uint32_t sb = smem_to_u32(sms);
    int t = threadIdx.x, lane = t & 31, wid = t >> 5;
    int wm = wid & 3, wn = wid >> 2;
    int bm = blockIdx.y * 128;
    int bn = blockIdx.x * 128;
    const int NC = NUM_NODE - 1;

    const uint4* Ah4 = (const uint4*)g_sel_hi;
    const uint4* Bh4 = (const uint4*)g_emb_hi;

    auto prefetch = [&](int stage, int kc) {
        for (int i = t; i < 1024; i += 256) {
            int arr = i >> 9;               // 0 Ah, 1 Bh
            int r   = (i >> 2) & 127;
            int v   = i & 3;
            uint32_t daddr = sb + stage * STG_S + arr * ASZ + r * (SKPH*2) + v * 16;
            if (arr == 0) {
                cp16(daddr, Ah4 + ((size_t)(bm + r) * 32 + kc * 4 + v), 16);
            } else {
                int er = bn + r + 1;
                size_t off = (size_t)(er < NUM_NODE ? er : 0) * 32 + kc * 4 + v;
                cp16(daddr, Bh4 + off, er < NUM_NODE ? 16u : 0u);
            }
        }
        asm volatile("cp.async.commit_group;" ::: "memory");
    };

    float c[2][8][4];
    #pragma unroll
    for (int mt = 0; mt < 2; mt++)
        #pragma unroll
        for (int nt = 0; nt < 8; nt++)
            #pragma unroll
            for (int q = 0; q < 4; q++) c[mt][nt][q] = 0.f;

    prefetch(0, 0);
    for (int kc = 0; kc < 8; kc++) {
        int s = kc & 1;
        if (kc + 1 < 8) {
            prefetch(1 - s, kc + 1);
            asm volatile("cp.async.wait_group 1;" ::: "memory");
        } else {
            asm volatile("cp.async.wait_group 0;" ::: "memory");
        }
        __syncthreads();
        uint32_t sAh = sb + s * STG_S;
        uint32_t sBh = sAh + ASZ;
        #pragma unroll
        for (int ks = 0; ks < 2; ks++) {
            int kbyte = ks * 32;
            uint32_t ah[2][4], bh[4][4];
            ldsm_A(ah[0], sAh, wm*32,      kbyte, lane);
            ldsm_A(ah[1], sAh, wm*32 + 16, kbyte, lane);
            #pragma unroll
            for (int g = 0; g < 4; g++)
                ldsm_B(bh[g], sBh, wn*64 + g*16, kbyte, lane);
            #pragma unroll
            for (int mt = 0; mt < 2; mt++)
                #pragma unroll
                for (int nt = 0; nt < 8; nt++)
                    mma_f16(c[mt][nt], ah[mt], &bh[nt >> 1][(nt & 1) * 2]);
        }
        __syncthreads();
    }

    #pragma unroll
    for (int mt = 0; mt < 2; mt++) {
        int r0 = bm + wm * 32 + mt * 16 + (lane >> 2);
        #pragma unroll
        for (int nt = 0; nt < 8; nt++) {
            int cc = bn + wn * 64 + nt * 8 + (lane & 3) * 2;
            size_t b0 = (size_t)r0 * NC + cc;
            size_t b1 = (size_t)(r0 + 8) * NC + cc;
            if (cc + 1 < NC) {
                out[b0] = c[mt][nt][0]; out[b0 + 1] = c[mt][nt][1];
                out[b1] = c[mt][nt][2]; out[b1 + 1] = c[mt][nt][3];
            } else if (cc < NC) {
                out[b0] = c[mt][nt][0];
                out[b1] = c[mt][nt][2];
            }
        }
    }
}

// ---------------- launch ----------------
extern "C" void kernel_launch(void* const* d_in, const int* in_sizes, int n_in,
                              void* d_out, int out_size) {
    const int*   iid     = (const int*)d_in[2];
    const int*   pid     = (const int*)d_in[3];
    const int*   tidp    = (const int*)d_in[4];
    const int*   i_src   = (const int*)d_in[5];
    const int*   i_dst   = (const int*)d_in[6];
    const int*   agg_src = (const int*)d_in[7];
    const int*   agg_dst = (const int*)d_in[8];
    const float* emb     = (const float*)d_in[9];
    const float* pos_emb = (const float*)d_in[10];
    const float* tgt_emb = (const float*)d_in[11];
    const float* p_w     = (const float*)d_in[12];
    const float* q_w     = (const float*)d_in[13];
    float* out = (float*)d_out;

    static bool attr_set = false;
    if (!attr_set) {
        cudaFuncSetAttribute(k_scores_mma, cudaFuncAttributeMaxDynamicSharedMemorySize, SMEM_S);
        cudaFuncSetAttribute(k_coef_mma,   cudaFuncAttributeMaxDynamicSharedMemorySize, SMEM_C);
        attr_set = true;
    }

    k_zero     <<<(N_ITEM + 255) / 256, 256>>>();
    k_split_emb<<<((size_t)NUM_NODE * DIM + 255) / 256, 256>>>(emb);
    k_split_q  <<<(DIM * DIM + 255) / 256, 256>>>(q_w);
    k_hist     <<<(E_INT + 255) / 256, 256>>>(i_dst, agg_dst);
    k_scan     <<<1, 1024>>>(0);
    k_scan     <<<1, 1024>>>(1);
    k_scatter  <<<(E_INT + 255) / 256, 256>>>(i_dst, agg_dst);
    k_attn     <<<N_ITEM / 8, 256>>>(iid, i_src, emb, p_w);
    k_posB     <<<NPOS, 256>>>(pos_emb, q_w);
    dim3 gc(2, N_ITEM / 128);
    k_coef_mma <<<gc, 256, SMEM_C>>>(agg_src, pid, agg_dst, tidp, tgt_emb);
    k_select   <<<N_TGT, 256>>>(agg_src);
    dim3 gs((NUM_NODE - 1 + 127) / 128, N_TGT / 128);
    k_scores_mma<<<gs, 256, SMEM_S>>>(out);
}

// round 7
// speedup vs baseline: 3.6621x; 1.2997x over previous
#include <cuda_runtime.h>
#include <cuda_fp16.h>
#include <cstdint>
#include <cstddef>

#define N_ITEM 81920
#define E_INT 327680
#define N_TGT 2048
#define NUM_NODE 50000
#define DIM 256
#define NPOS 200
#define ALPHA 0.2f

// ---------------- device scratch (static, no allocation) ----------------
__device__ __align__(16) float g_ft[(size_t)N_ITEM * DIM];
__device__ __align__(16) __half g_ft_hi[(size_t)N_ITEM * DIM];
__device__ __align__(16) __half g_ft_lo[(size_t)N_ITEM * DIM];
__device__ int   g_deg[N_ITEM];
__device__ int   g_rowoff[N_ITEM + 1];
__device__ int   g_cursor[N_ITEM];
__device__ int   g_esrc[E_INT];          // src row id (iid[i_src[e]]) sorted by dst
__device__ int   g_adeg[N_TGT];
__device__ int   g_arowoff[N_TGT + 1];
__device__ int   g_acursor[N_TGT];
__device__ int   g_aperm[N_ITEM];
__device__ int   g_bsum[328];
__device__ int   g_boff[328];
__device__ __align__(16) float g_B[NPOS * DIM];
__device__ float g_cpart[4][N_ITEM];     // coef partials: [ctaN*2 + warpN][row]
__device__ __align__(16) __half g_emb_hi[(size_t)NUM_NODE * DIM];
__device__ __align__(16) __half g_q_hi[DIM * DIM];
__device__ __align__(16) __half g_q_lo[DIM * DIM];
__device__ __align__(16) __half g_sel_hi[N_TGT * DIM];

__device__ __forceinline__ uint32_t smem_to_u32(const void* p) {
    uint32_t a;
    asm("{ .reg .u64 t; cvta.to.shared.u64 t, %1; cvt.u32.u64 %0, t; }" : "=r"(a) : "l"(p));
    return a;
}
__device__ __forceinline__ void cp16(uint32_t daddr, const void* src, uint32_t srcsize) {
    asm volatile("cp.async.cg.shared.global [%0], [%1], 16, %2;"
                 :: "r"(daddr), "l"(src), "r"(srcsize) : "memory");
}
__device__ __forceinline__ void mma_f16(float* c, const uint32_t* a, const uint32_t* b) {
    asm volatile("mma.sync.aligned.m16n8k16.row.col.f32.f16.f16.f32 "
                 "{%0,%1,%2,%3}, {%4,%5,%6,%7}, {%8,%9}, {%0,%1,%2,%3};"
                 : "+f"(c[0]), "+f"(c[1]), "+f"(c[2]), "+f"(c[3])
                 : "r"(a[0]), "r"(a[1]), "r"(a[2]), "r"(a[3]), "r"(b[0]), "r"(b[1]));
}
__device__ __forceinline__ void ldsm4(uint32_t* r, uint32_t addr) {
    asm volatile("ldmatrix.sync.aligned.m8n8.x4.shared.b16 {%0,%1,%2,%3}, [%4];"
                 : "=r"(r[0]), "=r"(r[1]), "=r"(r[2]), "=r"(r[3]) : "r"(addr));
}
// A 16x16 fp16 tile (row-major rows, 80B row stride) -> a-frag {a0,a1,a2,a3}
__device__ __forceinline__ void ldsm_A(uint32_t* r4, uint32_t base, int row0, int kbyte, int lane) {
    int m = lane >> 3, rr = lane & 7;
    uint32_t addr = base + (uint32_t)(row0 + ((m & 1) << 3) + rr) * 80u + kbyte + ((m >> 1) << 4);
    ldsm4(r4, addr);
}
// B: 16 n-rows x 16 k (row-major n rows, 80B stride) -> {b0(nt0),b1(nt0),b0(nt1),b1(nt1)}
__device__ __forceinline__ void ldsm_B(uint32_t* r4, uint32_t base, int n0, int kbyte, int lane) {
    int m = lane >> 3, rr = lane & 7;
    uint32_t addr = base + (uint32_t)(n0 + ((m >> 1) << 3) + rr) * 80u + kbyte + ((m & 1) << 4);
    ldsm4(r4, addr);
}

// ---------------- fused prep: zero counters + fp16 splits ----------------
__global__ void k_prep(const float* __restrict__ emb, const float* __restrict__ q_w) {
    size_t i = (size_t)blockIdx.x * blockDim.x + threadIdx.x;
    if (i < (size_t)NUM_NODE * DIM) g_emb_hi[i] = __float2half(emb[i]);
    if (i < DIM * DIM) {
        int d = (int)(i >> 8), k = (int)(i & 255);
        float x = q_w[(size_t)d * (2 * DIM) + k];
        __half h = __float2half(x);
        g_q_hi[i] = h;
        g_q_lo[i] = __float2half(x - __half2float(h));
    }
    if (i < N_ITEM) g_deg[i] = 0;
    if (i < N_TGT)  g_adeg[i] = 0;
}

// ---------------- histogram ----------------
__global__ void k_hist(const int* __restrict__ i_dst, const int* __restrict__ agg_dst) {
    int i = blockIdx.x * blockDim.x + threadIdx.x;
    if (i < E_INT)  atomicAdd(&g_deg[i_dst[i]], 1);
    if (i < N_ITEM) atomicAdd(&g_adeg[agg_dst[i]], 1);
}

// ---------------- 3-phase scan: blocks 0..319 item chunks, 320..327 tgt chunks ----------------
__global__ void __launch_bounds__(256) k_scanA() {
    int b = blockIdx.x, t = threadIdx.x;
    __shared__ int s[256];
    int v = (b < 320) ? g_deg[b * 256 + t] : g_adeg[(b - 320) * 256 + t];
    s[t] = v;
    __syncthreads();
    #pragma unroll
    for (int o = 128; o; o >>= 1) {
        if (t < o) s[t] += s[t + o];
        __syncthreads();
    }
    if (t == 0) g_bsum[b] = s[0];
}
__global__ void __launch_bounds__(512) k_scanB() {
    __shared__ int s[512];
    int t = threadIdx.x;
    int v = (t < 320) ? g_bsum[t] : 0;
    s[t] = v;
    __syncthreads();
    for (int o = 1; o < 512; o <<= 1) {
        int u = (t >= o) ? s[t - o] : 0;
        __syncthreads();
        if (t >= o) s[t] += u;
        __syncthreads();
    }
    if (t < 320) g_boff[t] = s[t] - v;      // exclusive
    if (t == 0) {
        int run = 0;
        #pragma unroll
        for (int i = 0; i < 8; i++) { g_boff[320 + i] = run; run += g_bsum[320 + i]; }
    }
}
__global__ void __launch_bounds__(256) k_scanC() {
    int b = blockIdx.x, t = threadIdx.x;
    __shared__ int s[256];
    int base = g_boff[b];
    int idx, v;
    if (b < 320) { idx = b * 256 + t; v = g_deg[idx]; }
    else         { idx = (b - 320) * 256 + t; v = g_adeg[idx]; }
    s[t] = v;
    __syncthreads();
    for (int o = 1; o < 256; o <<= 1) {
        int u = (t >= o) ? s[t - o] : 0;
        __syncthreads();
        if (t >= o) s[t] += u;
        __syncthreads();
    }
    int excl = base + s[t] - v;
    if (b < 320) { g_rowoff[idx] = excl; g_cursor[idx] = excl; }
    else         { g_arowoff[idx] = excl; g_acursor[idx] = excl; }
    if (b == 0 && t == 0) { g_rowoff[N_ITEM] = E_INT; g_arowoff[N_TGT] = N_ITEM; }
}

// ---------------- scatter (stores src ROW id directly for attn) ----------------
__global__ void k_scatter(const int* __restrict__ i_dst, const int* __restrict__ i_src,
                          const int* __restrict__ iid, const int* __restrict__ agg_dst) {
    int i = blockIdx.x * blockDim.x + threadIdx.x;
    if (i < E_INT) {
        int d = i_dst[i];
        int p = atomicAdd(&g_cursor[d], 1);
        g_esrc[p] = iid[i_src[i]];
    }
    if (i < N_ITEM) {
        int d = agg_dst[i];
        g_aperm[atomicAdd(&g_acursor[d], 1)] = i;
    }
}

// ---------------- single-pass attention (softmax shift-invariant; |logit|~4e-3) ----------------
__global__ void __launch_bounds__(256) k_attn(const int* __restrict__ iid,
                                              const float* __restrict__ emb,
                                              const float* __restrict__ p_w) {
    int gw   = (blockIdx.x * blockDim.x + threadIdx.x) >> 5;
    int lane = threadIdx.x & 31;
    if (gw >= N_ITEM) return;
    int v = gw;
    const float4* embv = (const float4*)emb;
    int c0 = lane * 2;
    size_t rv = (size_t)iid[v] * (DIM / 4);
    float4 hd0 = embv[rv + c0];
    float4 hd1 = embv[rv + c0 + 1];
    float4 pw0 = ((const float4*)p_w)[c0];
    float4 pw1 = ((const float4*)p_w)[c0 + 1];
    // fold p_w into dst row once
    hd0.x *= pw0.x; hd0.y *= pw0.y; hd0.z *= pw0.z; hd0.w *= pw0.w;
    hd1.x *= pw1.x; hd1.y *= pw1.y; hd1.z *= pw1.z; hd1.w *= pw1.w;
    int rs = g_rowoff[v], re = g_rowoff[v + 1];

    float den = 0.f;
    float4 a0 = make_float4(0.f,0.f,0.f,0.f), a1 = make_float4(0.f,0.f,0.f,0.f);
    for (int idx = rs; idx < re; idx++) {
        size_t ru = (size_t)g_esrc[idx] * (DIM / 4);
        float4 hs0 = embv[ru + c0];
        float4 hs1 = embv[ru + c0 + 1];
        float p = hs0.x*hd0.x + hs0.y*hd0.y + hs0.z*hd0.z + hs0.w*hd0.w
                + hs1.x*hd1.x + hs1.y*hd1.y + hs1.z*hd1.z + hs1.w*hd1.w;
        #pragma unroll
        for (int o = 16; o; o >>= 1) p += __shfl_xor_sync(0xffffffffu, p, o);
        p = (p >= 0.f) ? p : ALPHA * p;
        float ex = __expf(p);
        den += ex;
        a0.x += ex*hs0.x; a0.y += ex*hs0.y; a0.z += ex*hs0.z; a0.w += ex*hs0.w;
        a1.x += ex*hs1.x; a1.y += ex*hs1.y; a1.z += ex*hs1.z; a1.w += ex*hs1.w;
    }
    float inv = 1.f / fmaxf(den, 1e-12f);
    float o[8] = { a0.x*inv, a0.y*inv, a0.z*inv, a0.w*inv,
                   a1.x*inv, a1.y*inv, a1.z*inv, a1.w*inv };
    ((float4*)g_ft)[(size_t)v*(DIM/4) + c0]     = make_float4(o[0], o[1], o[2], o[3]);
    ((float4*)g_ft)[(size_t)v*(DIM/4) + c0 + 1] = make_float4(o[4], o[5], o[6], o[7]);
    union { __half h[8]; uint4 u; } ph, pl;
    #pragma unroll
    for (int q = 0; q < 8; q++) {
        __half h = __float2half(o[q]);
        ph.h[q] = h;
        pl.h[q] = __float2half(o[q] - __half2float(h));
    }
    ((uint4*)g_ft_hi)[(size_t)v * 32 + lane] = ph.u;
    ((uint4*)g_ft_lo)[(size_t)v * 32 + lane] = pl.u;
}

// ---------------- B = pos_emb @ q_w[:,256:].T ----------------
__global__ void k_posB(const float* __restrict__ pos_emb, const float* __restrict__ q_w) {
    int p = blockIdx.x, d = threadIdx.x;
    __shared__ float sp[DIM];
    sp[d] = pos_emb[p * DIM + d];
    __syncthreads();
    const float4* q4 = (const float4*)(q_w + (size_t)d * (2 * DIM) + DIM);
    float acc = 0.f;
    #pragma unroll 8
    for (int k = 0; k < DIM / 4; k++) {
        float4 q = q4[k];
        acc += sp[4*k]*q.x + sp[4*k+1]*q.y + sp[4*k+2]*q.z + sp[4*k+3]*q.w;
    }
    g_B[p * DIM + d] = acc;
}

// ================= k_coef via mma (3-term fp16 split) =================
#define SKPH 40
#define ASZ (128 * SKPH * 2)      // 10240 B per array per stage
#define STG_C (4 * ASZ)           // 40960
#define OFF_SJ   (2 * STG_C)      // 81920
#define OFF_SPID (OFF_SJ + 512)
#define OFF_ST   (OFF_SPID + 512)
#define OFF_BPOS (OFF_ST + 512)   // 83456
#define SMEM_C   (OFF_BPOS + 128 * 132 * 4)   // 151040

__global__ void __launch_bounds__(256) k_coef_mma(const int* __restrict__ agg_src,
                                                  const int* __restrict__ pid,
                                                  const int* __restrict__ agg_dst,
                                                  const int* __restrict__ tid,
                                                  const float* __restrict__ tgt_emb) {
    extern __shared__ char smc[];
    uint32_t sb = smem_to_u32(smc);
    int* sj   = (int*)(smc + OFF_SJ);
    int* spid = (int*)(smc + OFF_SPID);
    int* stt  = (int*)(smc + OFF_ST);
    float* sBpos = (float*)(smc + OFF_BPOS);

    int t = threadIdx.x, lane = t & 31, wid = t >> 5;
    int wm = wid & 3, wn = wid >> 2;
    int bn = blockIdx.x * 128;               // d-tile (0 or 128)
    int j0 = blockIdx.y * 128;

    if (t < 128) {
        sj[t]   = agg_src[j0 + t];
        spid[t] = pid[j0 + t];
        stt[t]  = tid[agg_dst[j0 + t]];
    }
    __syncthreads();

    const uint4* Fh4 = (const uint4*)g_ft_hi;
    const uint4* Fl4 = (const uint4*)g_ft_lo;
    const uint4* Qh4 = (const uint4*)g_q_hi;
    const uint4* Ql4 = (const uint4*)g_q_lo;

    auto prefetch = [&](int stage, int kc) {
        for (int i = t; i < 2048; i += 256) {
            int arr = i >> 9;               // 0 Ah,1 Al,2 Bh,3 Bl
            int r   = (i >> 2) & 127;
            int v   = i & 3;
            uint32_t daddr = sb + stage * STG_C + arr * ASZ + r * (SKPH*2) + v * 16;
            if (arr < 2) {
                size_t off = (size_t)sj[r] * 32 + kc * 4 + v;
                cp16(daddr, (arr == 0 ? Fh4 : Fl4) + off, 16);
            } else {
                size_t off = (size_t)(bn + r) * 32 + kc * 4 + v;
                cp16(daddr, (arr == 2 ? Qh4 : Ql4) + off, 16);
            }
        }
        asm volatile("cp.async.commit_group;" ::: "memory");
    };

    float c[2][8][4];
    #pragma unroll
    for (int mt = 0; mt < 2; mt++)
        #pragma unroll
        for (int nt = 0; nt < 8; nt++)
            #pragma unroll
            for (int q = 0; q < 4; q++) c[mt][nt][q] = 0.f;

    prefetch(0, 0);
    for (int kc = 0; kc < 8; kc++) {
        int s = kc & 1;
        if (kc + 1 < 8) {
            prefetch(1 - s, kc + 1);
            asm volatile("cp.async.wait_group 1;" ::: "memory");
        } else {
            asm volatile("cp.async.wait_group 0;" ::: "memory");
        }
        __syncthreads();
        uint32_t sAh = sb + s * STG_C;
        uint32_t sAl = sAh + ASZ;
        uint32_t sBh = sAl + ASZ;
        uint32_t sBl = sBh + ASZ;
        #pragma unroll
        for (int ks = 0; ks < 2; ks++) {
            int kbyte = ks * 32;
            uint32_t ah[2][4], al[2][4], bh[4][4], bl[4][4];
            ldsm_A(ah[0], sAh, wm*32,      kbyte, lane);
            ldsm_A(ah[1], sAh, wm*32 + 16, kbyte, lane);
            ldsm_A(al[0], sAl, wm*32,      kbyte, lane);
            ldsm_A(al[1], sAl, wm*32 + 16, kbyte, lane);
            #pragma unroll
            for (int g = 0; g < 4; g++) {
                ldsm_B(bh[g], sBh, wn*64 + g*16, kbyte, lane);
                ldsm_B(bl[g], sBl, wn*64 + g*16, kbyte, lane);
            }
            #pragma unroll
            for (int mt = 0; mt < 2; mt++)
                #pragma unroll
                for (int nt = 0; nt < 8; nt++) {
                    const uint32_t* ph = &bh[nt >> 1][(nt & 1) * 2];
                    const uint32_t* pl2 = &bl[nt >> 1][(nt & 1) * 2];
                    mma_f16(c[mt][nt], ah[mt], ph);
                    mma_f16(c[mt][nt], ah[mt], pl2);
                    mma_f16(c[mt][nt], al[mt], ph);
                }
        }
        __syncthreads();
    }

    for (int i = t; i < 128 * 32; i += 256) {
        int r = i >> 5, v = i & 31;
        float4 val = ((const float4*)g_B)[(size_t)spid[r] * 64 + (bn >> 2) + v];
        *(float4*)&sBpos[r * 132 + v * 4] = val;
    }
    __syncthreads();

    int slot = blockIdx.x * 2 + wn;
    #pragma unroll
    for (int mt = 0; mt < 2; mt++)
        #pragma unroll
        for (int half = 0; half < 2; half++) {
            int rl = wm*32 + mt*16 + half*8 + (lane >> 2);
            const float* htr = tgt_emb + (size_t)stt[rl] * DIM + bn;
            float p = 0.f;
            #pragma unroll
            for (int nt = 0; nt < 8; nt++) {
                int cl = wn*64 + nt*8 + (lane & 3)*2;
                float y0 = c[mt][nt][half*2 + 0] + sBpos[rl*132 + cl];
                float y1 = c[mt][nt][half*2 + 1] + sBpos[rl*132 + cl + 1];
                p += tanhf(y0) * htr[cl] + tanhf(y1) * htr[cl + 1];
            }
            p += __shfl_xor_sync(0xffffffffu, p, 1);
            p += __shfl_xor_sync(0xffffffffu, p, 2);
            if ((lane & 3) == 0) g_cpart[slot][j0 + rl] = p;
        }
}

// ---------------- select (sums 4 coef partials deterministically) ----------------
__global__ void k_select(const int* __restrict__ agg_src) {
    int tgt = blockIdx.x;
    int d = threadIdx.x;
    float acc = 0.f;
    int rs = g_arowoff[tgt], re = g_arowoff[tgt + 1];
    for (int idx = rs; idx < re; idx++) {
        int j = g_aperm[idx];
        float coef = (g_cpart[0][j] + g_cpart[1][j]) + (g_cpart[2][j] + g_cpart[3][j]);
        acc += coef * g_ft[(size_t)agg_src[j] * DIM + d];
    }
    g_sel_hi[tgt * DIM + d] = __float2half(acc);
}

// ================= scores: single-term fp16 (Ah*Bh), 3-stage pipeline =================
#define STG_S (2 * ASZ)           // 20480
#define SMEM_S (3 * STG_S)        // 61440

__global__ void __launch_bounds__(256) k_scores_mma(float* __restrict__ out) {
    extern __shared__ char sms[];
    uint32_t sb = smem_to_u32(sms);
    int t = threadIdx.x, lane = t & 31, wid = t >> 5;
    int wm = wid & 3, wn = wid >> 2;
    int bm = blockIdx.y * 128;
    int bn = blockIdx.x * 128;
    const int NC = NUM_NODE - 1;

    const uint4* Ah4 = (const uint4*)g_sel_hi;
    const uint4* Bh4 = (const uint4*)g_emb_hi;

    auto prefetch = [&](int stage, int kc) {
        for (int i = t; i < 1024; i += 256) {
            int arr = i >> 9;               // 0 Ah, 1 Bh
            int r   = (i >> 2) & 127;
            int v   = i & 3;
            uint32_t daddr = sb + stage * STG_S + arr * ASZ + r * (SKPH*2) + v * 16;
            if (arr == 0) {
                cp16(daddr, Ah4 + ((size_t)(bm + r) * 32 + kc * 4 + v), 16);
            } else {
                int er = bn + r + 1;
                size_t off = (size_t)(er < NUM_NODE ? er : 0) * 32 + kc * 4 + v;
                cp16(daddr, Bh4 + off, er < NUM_NODE ? 16u : 0u);
            }
        }
        asm volatile("cp.async.commit_group;" ::: "memory");
    };

    float c[2][8][4];
    #pragma unroll
    for (int mt = 0; mt < 2; mt++)
        #pragma unroll
        for (int nt = 0; nt < 8; nt++)
            #pragma unroll
            for (int q = 0; q < 4; q++) c[mt][nt][q] = 0.f;

    prefetch(0, 0);
    prefetch(1, 1);
    for (int kc = 0; kc < 8; kc++) {
        if (kc < 7) asm volatile("cp.async.wait_group 1;" ::: "memory");
        else        asm volatile("cp.async.wait_group 0;" ::: "memory");
        __syncthreads();
        if (kc + 2 < 8) prefetch((kc + 2) % 3, kc + 2);
        int s = kc % 3;
        uint32_t sAh = sb + s * STG_S;
        uint32_t sBh = sAh + ASZ;
        #pragma unroll
        for (int ks = 0; ks < 2; ks++) {
            int kbyte = ks * 32;
            uint32_t ah[2][4], bh[4][4];
            ldsm_A(ah[0], sAh, wm*32,      kbyte, lane);
            ldsm_A(ah[1], sAh, wm*32 + 16, kbyte, lane);
            #pragma unroll
            for (int g = 0; g < 4; g++)
                ldsm_B(bh[g], sBh, wn*64 + g*16, kbyte, lane);
            #pragma unroll
            for (int mt = 0; mt < 2; mt++)
                #pragma unroll
                for (int nt = 0; nt < 8; nt++)
                    mma_f16(c[mt][nt], ah[mt], &bh[nt >> 1][(nt & 1) * 2]);
        }
    }

    #pragma unroll
    for (int mt = 0; mt < 2; mt++) {
        int r0 = bm + wm * 32 + mt * 16 + (lane >> 2);
        #pragma unroll
        for (int nt = 0; nt < 8; nt++) {
            int cc = bn + wn * 64 + nt * 8 + (lane & 3) * 2;
            size_t b0 = (size_t)r0 * NC + cc;
            size_t b1 = (size_t)(r0 + 8) * NC + cc;
            if (cc + 1 < NC) {
                out[b0] = c[mt][nt][0]; out[b0 + 1] = c[mt][nt][1];
                out[b1] = c[mt][nt][2]; out[b1 + 1] = c[mt][nt][3];
            } else if (cc < NC) {
                out[b0] = c[mt][nt][0];
                out[b1] = c[mt][nt][2];
            }
        }
    }
}

// ---------------- launch ----------------
extern "C" void kernel_launch(void* const* d_in, const int* in_sizes, int n_in,
                              void* d_out, int out_size) {
    const int*   iid     = (const int*)d_in[2];
    const int*   pid     = (const int*)d_in[3];
    const int*   tidp    = (const int*)d_in[4];
    const int*   i_src   = (const int*)d_in[5];
    const int*   i_dst   = (const int*)d_in[6];
    const int*   agg_src = (const int*)d_in[7];
    const int*   agg_dst = (const int*)d_in[8];
    const float* emb     = (const float*)d_in[9];
    const float* pos_emb = (const float*)d_in[10];
    const float* tgt_emb = (const float*)d_in[11];
    const float* p_w     = (const float*)d_in[12];
    const float* q_w     = (const float*)d_in[13];
    float* out = (float*)d_out;

    static bool attr_set = false;
    if (!attr_set) {
        cudaFuncSetAttribute(k_scores_mma, cudaFuncAttributeMaxDynamicSharedMemorySize, SMEM_S);
        cudaFuncSetAttribute(k_coef_mma,   cudaFuncAttributeMaxDynamicSharedMemorySize, SMEM_C);
        attr_set = true;
    }

    k_prep    <<<(NUM_NODE * DIM + 255) / 256, 256>>>(emb, q_w);
    k_hist    <<<(E_INT + 255) / 256, 256>>>(i_dst, agg_dst);
    k_scanA   <<<328, 256>>>();
    k_scanB   <<<1, 512>>>();
    k_scanC   <<<328, 256>>>();
    k_scatter <<<(E_INT + 255) / 256, 256>>>(i_dst, i_src, iid, agg_dst);
    k_attn    <<<N_ITEM / 8, 256>>>(iid, emb, p_w);
    k_posB    <<<NPOS, 256>>>(pos_emb, q_w);
    dim3 gc(2, N_ITEM / 128);
    k_coef_mma<<<gc, 256, SMEM_C>>>(agg_src, pid, agg_dst, tidp, tgt_emb);
    k_select  <<<N_TGT, 256>>>(agg_src);
    dim3 gs((NUM_NODE - 1 + 127) / 128, N_TGT / 128);
    k_scores_mma<<<gs, 256, SMEM_S>>>(out);
}

// round 8
// speedup vs baseline: 3.8429x; 1.0494x over previous
#include <cuda_runtime.h>
#include <cuda_fp16.h>
#include <cstdint>
#include <cstddef>

#define N_ITEM 81920
#define E_INT 327680
#define N_TGT 2048
#define NUM_NODE 50000
#define DIM 256
#define NPOS 200
#define ALPHA 0.2f

// ---------------- device scratch (static, no allocation) ----------------
__device__ __align__(16) float g_ft[(size_t)N_ITEM * DIM];
__device__ __align__(16) __half g_ft_hi[(size_t)N_ITEM * DIM];
__device__ __align__(16) __half g_ft_lo[(size_t)N_ITEM * DIM];
__device__ int   g_deg[N_ITEM];
__device__ int   g_rowoff[N_ITEM + 1];
__device__ int   g_cursor[N_ITEM];
__device__ int   g_esrc[E_INT];          // src row id (iid[i_src[e]]) sorted by dst
__device__ int   g_adeg[N_TGT];
__device__ int   g_arowoff[N_TGT + 1];
__device__ int   g_acursor[N_TGT];
__device__ int   g_aperm[N_ITEM];
__device__ int   g_bsum[328];
__device__ int   g_boff[328];
__device__ __align__(16) float g_B[NPOS * DIM];
__device__ float g_cpart[4][N_ITEM];     // coef partials: [ctaN*2 + warpN][row]
__device__ __align__(16) __half g_emb_hi[(size_t)NUM_NODE * DIM];
__device__ __align__(16) __half g_q_hi[DIM * DIM];
__device__ __align__(16) __half g_sel_hi[N_TGT * DIM];

__device__ __forceinline__ uint32_t smem_to_u32(const void* p) {
    uint32_t a;
    asm("{ .reg .u64 t; cvta.to.shared.u64 t, %1; cvt.u32.u64 %0, t; }" : "=r"(a) : "l"(p));
    return a;
}
__device__ __forceinline__ void cp16(uint32_t daddr, const void* src, uint32_t srcsize) {
    asm volatile("cp.async.cg.shared.global [%0], [%1], 16, %2;"
                 :: "r"(daddr), "l"(src), "r"(srcsize) : "memory");
}
__device__ __forceinline__ void mma_f16(float* c, const uint32_t* a, const uint32_t* b) {
    asm volatile("mma.sync.aligned.m16n8k16.row.col.f32.f16.f16.f32 "
                 "{%0,%1,%2,%3}, {%4,%5,%6,%7}, {%8,%9}, {%0,%1,%2,%3};"
                 : "+f"(c[0]), "+f"(c[1]), "+f"(c[2]), "+f"(c[3])
                 : "r"(a[0]), "r"(a[1]), "r"(a[2]), "r"(a[3]), "r"(b[0]), "r"(b[1]));
}
__device__ __forceinline__ void ldsm4(uint32_t* r, uint32_t addr) {
    asm volatile("ldmatrix.sync.aligned.m8n8.x4.shared.b16 {%0,%1,%2,%3}, [%4];"
                 : "=r"(r[0]), "=r"(r[1]), "=r"(r[2]), "=r"(r[3]) : "r"(addr));
}
// A 16x16 fp16 tile (row-major rows, 80B row stride) -> a-frag {a0,a1,a2,a3}
__device__ __forceinline__ void ldsm_A(uint32_t* r4, uint32_t base, int row0, int kbyte, int lane) {
    int m = lane >> 3, rr = lane & 7;
    uint32_t addr = base + (uint32_t)(row0 + ((m & 1) << 3) + rr) * 80u + kbyte + ((m >> 1) << 4);
    ldsm4(r4, addr);
}
// B: 16 n-rows x 16 k (row-major n rows, 80B stride) -> {b0(nt0),b1(nt0),b0(nt1),b1(nt1)}
__device__ __forceinline__ void ldsm_B(uint32_t* r4, uint32_t base, int n0, int kbyte, int lane) {
    int m = lane >> 3, rr = lane & 7;
    uint32_t addr = base + (uint32_t)(n0 + ((m >> 1) << 3) + rr) * 80u + kbyte + ((m & 1) << 4);
    ldsm4(r4, addr);
}

// ---------------- fused prep: zero counters + fp16 splits ----------------
__global__ void k_prep(const float* __restrict__ emb, const float* __restrict__ q_w) {
    size_t i = (size_t)blockIdx.x * blockDim.x + threadIdx.x;
    if (i < (size_t)NUM_NODE * DIM) g_emb_hi[i] = __float2half(emb[i]);
    if (i < DIM * DIM) {
        int d = (int)(i >> 8), k = (int)(i & 255);
        g_q_hi[i] = __float2half(q_w[(size_t)d * (2 * DIM) + k]);
    }
    if (i < N_ITEM) g_deg[i] = 0;
    if (i < N_TGT)  g_adeg[i] = 0;
}

// ---------------- histogram ----------------
__global__ void k_hist(const int* __restrict__ i_dst, const int* __restrict__ agg_dst) {
    int i = blockIdx.x * blockDim.x + threadIdx.x;
    if (i < E_INT)  atomicAdd(&g_deg[i_dst[i]], 1);
    if (i < N_ITEM) atomicAdd(&g_adeg[agg_dst[i]], 1);
}

// ---------------- 3-phase scan: blocks 0..319 item chunks, 320..327 tgt chunks ----------------
__global__ void __launch_bounds__(256) k_scanA() {
    int b = blockIdx.x, t = threadIdx.x;
    __shared__ int s[256];
    int v = (b < 320) ? g_deg[b * 256 + t] : g_adeg[(b - 320) * 256 + t];
    s[t] = v;
    __syncthreads();
    #pragma unroll
    for (int o = 128; o; o >>= 1) {
        if (t < o) s[t] += s[t + o];
        __syncthreads();
    }
    if (t == 0) g_bsum[b] = s[0];
}
__global__ void __launch_bounds__(512) k_scanB() {
    __shared__ int s[512];
    int t = threadIdx.x;
    int v = (t < 320) ? g_bsum[t] : 0;
    s[t] = v;
    __syncthreads();
    for (int o = 1; o < 512; o <<= 1) {
        int u = (t >= o) ? s[t - o] : 0;
        __syncthreads();
        if (t >= o) s[t] += u;
        __syncthreads();
    }
    if (t < 320) g_boff[t] = s[t] - v;      // exclusive
    if (t == 0) {
        int run = 0;
        #pragma unroll
        for (int i = 0; i < 8; i++) { g_boff[320 + i] = run; run += g_bsum[320 + i]; }
    }
}
__global__ void __launch_bounds__(256) k_scanC() {
    int b = blockIdx.x, t = threadIdx.x;
    __shared__ int s[256];
    int base = g_boff[b];
    int idx, v;
    if (b < 320) { idx = b * 256 + t; v = g_deg[idx]; }
    else         { idx = (b - 320) * 256 + t; v = g_adeg[idx]; }
    s[t] = v;
    __syncthreads();
    for (int o = 1; o < 256; o <<= 1) {
        int u = (t >= o) ? s[t - o] : 0;
        __syncthreads();
        if (t >= o) s[t] += u;
        __syncthreads();
    }
    int excl = base + s[t] - v;
    if (b < 320) { g_rowoff[idx] = excl; g_cursor[idx] = excl; }
    else         { g_arowoff[idx] = excl; g_acursor[idx] = excl; }
    if (b == 0 && t == 0) { g_rowoff[N_ITEM] = E_INT; g_arowoff[N_TGT] = N_ITEM; }
}

// ---------------- scatter (stores src ROW id directly for attn) ----------------
__global__ void k_scatter(const int* __restrict__ i_dst, const int* __restrict__ i_src,
                          const int* __restrict__ iid, const int* __restrict__ agg_dst) {
    int i = blockIdx.x * blockDim.x + threadIdx.x;
    if (i < E_INT) {
        int d = i_dst[i];
        int p = atomicAdd(&g_cursor[d], 1);
        g_esrc[p] = iid[i_src[i]];
    }
    if (i < N_ITEM) {
        int d = agg_dst[i];
        g_aperm[atomicAdd(&g_acursor[d], 1)] = i;
    }
}

// ---------------- single-pass attention, edge loop unrolled x2 ----------------
__global__ void __launch_bounds__(256) k_attn(const int* __restrict__ iid,
                                              const float* __restrict__ emb,
                                              const float* __restrict__ p_w) {
    int gw   = (blockIdx.x * blockDim.x + threadIdx.x) >> 5;
    int lane = threadIdx.x & 31;
    if (gw >= N_ITEM) return;
    int v = gw;
    const float4* embv = (const float4*)emb;
    int c0 = lane * 2;
    size_t rv = (size_t)iid[v] * (DIM / 4);
    float4 hd0 = embv[rv + c0];
    float4 hd1 = embv[rv + c0 + 1];
    float4 pw0 = ((const float4*)p_w)[c0];
    float4 pw1 = ((const float4*)p_w)[c0 + 1];
    hd0.x *= pw0.x; hd0.y *= pw0.y; hd0.z *= pw0.z; hd0.w *= pw0.w;
    hd1.x *= pw1.x; hd1.y *= pw1.y; hd1.z *= pw1.z; hd1.w *= pw1.w;
    int rs = g_rowoff[v], re = g_rowoff[v + 1];

    float den = 0.f;
    float4 a0 = make_float4(0.f,0.f,0.f,0.f), a1 = make_float4(0.f,0.f,0.f,0.f);
    int idx = rs;
    for (; idx + 1 < re; idx += 2) {
        size_t ruA = (size_t)g_esrc[idx] * (DIM / 4);
        size_t ruB = (size_t)g_esrc[idx + 1] * (DIM / 4);
        float4 sA0 = embv[ruA + c0], sA1 = embv[ruA + c0 + 1];
        float4 sB0 = embv[ruB + c0], sB1 = embv[ruB + c0 + 1];
        float pA = sA0.x*hd0.x + sA0.y*hd0.y + sA0.z*hd0.z + sA0.w*hd0.w
                 + sA1.x*hd1.x + sA1.y*hd1.y + sA1.z*hd1.z + sA1.w*hd1.w;
        float pB = sB0.x*hd0.x + sB0.y*hd0.y + sB0.z*hd0.z + sB0.w*hd0.w
                 + sB1.x*hd1.x + sB1.y*hd1.y + sB1.z*hd1.z + sB1.w*hd1.w;
        #pragma unroll
        for (int o = 16; o; o >>= 1) {
            pA += __shfl_xor_sync(0xffffffffu, pA, o);
            pB += __shfl_xor_sync(0xffffffffu, pB, o);
        }
        pA = (pA >= 0.f) ? pA : ALPHA * pA;
        pB = (pB >= 0.f) ? pB : ALPHA * pB;
        float eA = __expf(pA), eB = __expf(pB);
        den += eA + eB;
        a0.x += eA*sA0.x + eB*sB0.x; a0.y += eA*sA0.y + eB*sB0.y;
        a0.z += eA*sA0.z + eB*sB0.z; a0.w += eA*sA0.w + eB*sB0.w;
        a1.x += eA*sA1.x + eB*sB1.x; a1.y += eA*sA1.y + eB*sB1.y;
        a1.z += eA*sA1.z + eB*sB1.z; a1.w += eA*sA1.w + eB*sB1.w;
    }
    if (idx < re) {
        size_t ru = (size_t)g_esrc[idx] * (DIM / 4);
        float4 hs0 = embv[ru + c0], hs1 = embv[ru + c0 + 1];
        float p = hs0.x*hd0.x + hs0.y*hd0.y + hs0.z*hd0.z + hs0.w*hd0.w
                + hs1.x*hd1.x + hs1.y*hd1.y + hs1.z*hd1.z + hs1.w*hd1.w;
        #pragma unroll
        for (int o = 16; o; o >>= 1) p += __shfl_xor_sync(0xffffffffu, p, o);
        p = (p >= 0.f) ? p : ALPHA * p;
        float ex = __expf(p);
        den += ex;
        a0.x += ex*hs0.x; a0.y += ex*hs0.y; a0.z += ex*hs0.z; a0.w += ex*hs0.w;
        a1.x += ex*hs1.x; a1.y += ex*hs1.y; a1.z += ex*hs1.z; a1.w += ex*hs1.w;
    }
    float inv = 1.f / fmaxf(den, 1e-12f);
    float o[8] = { a0.x*inv, a0.y*inv, a0.z*inv, a0.w*inv,
                   a1.x*inv, a1.y*inv, a1.z*inv, a1.w*inv };
    ((float4*)g_ft)[(size_t)v*(DIM/4) + c0]     = make_float4(o[0], o[1], o[2], o[3]);
    ((float4*)g_ft)[(size_t)v*(DIM/4) + c0 + 1] = make_float4(o[4], o[5], o[6], o[7]);
    union { __half h[8]; uint4 u; } ph, pl;
    #pragma unroll
    for (int q = 0; q < 8; q++) {
        __half h = __float2half(o[q]);
        ph.h[q] = h;
        pl.h[q] = __float2half(o[q] - __half2float(h));
    }
    ((uint4*)g_ft_hi)[(size_t)v * 32 + lane] = ph.u;
    ((uint4*)g_ft_lo)[(size_t)v * 32 + lane] = pl.u;
}

// ---------------- B = pos_emb @ q_w[:,256:].T ----------------
__global__ void k_posB(const float* __restrict__ pos_emb, const float* __restrict__ q_w) {
    int p = blockIdx.x, d = threadIdx.x;
    __shared__ float sp[DIM];
    sp[d] = pos_emb[p * DIM + d];
    __syncthreads();
    const float4* q4 = (const float4*)(q_w + (size_t)d * (2 * DIM) + DIM);
    float acc = 0.f;
    #pragma unroll 8
    for (int k = 0; k < DIM / 4; k++) {
        float4 q = q4[k];
        acc += sp[4*k]*q.x + sp[4*k+1]*q.y + sp[4*k+2]*q.z + sp[4*k+3]*q.w;
    }
    g_B[p * DIM + d] = acc;
}

// ================= k_coef via mma (2-term fp16 split: ft_hi*q + ft_lo*q) =================
#define SKPH 40
#define ASZ (128 * SKPH * 2)      // 10240 B per array per stage
#define STG_C (3 * ASZ)           // 30720 (Ah, Al, Bh)
#define OFF_SJ   (3 * STG_C)      // 92160
#define OFF_SPID (OFF_SJ + 512)
#define OFF_ST   (OFF_SPID + 512)
#define OFF_BPOS (OFF_ST + 512)   // 93696
#define SMEM_C   (OFF_BPOS + 128 * 132 * 4)   // 161280

__global__ void __launch_bounds__(256) k_coef_mma(const int* __restrict__ agg_src,
                                                  const int* __restrict__ pid,
                                                  const int* __restrict__ agg_dst,
                                                  const int* __restrict__ tid,
                                                  const float* __restrict__ tgt_emb) {
    extern __shared__ char smc[];
    uint32_t sb = smem_to_u32(smc);
    int* sj   = (int*)(smc + OFF_SJ);
    int* spid = (int*)(smc + OFF_SPID);
    int* stt  = (int*)(smc + OFF_ST);
    float* sBpos = (float*)(smc + OFF_BPOS);

    int t = threadIdx.x, lane = t & 31, wid = t >> 5;
    int wm = wid & 3, wn = wid >> 2;
    int bn = blockIdx.x * 128;               // d-tile (0 or 128)
    int j0 = blockIdx.y * 128;

    if (t < 128) {
        sj[t]   = agg_src[j0 + t];
        spid[t] = pid[j0 + t];
        stt[t]  = tid[agg_dst[j0 + t]];
    }
    __syncthreads();

    const uint4* Fh4 = (const uint4*)g_ft_hi;
    const uint4* Fl4 = (const uint4*)g_ft_lo;
    const uint4* Qh4 = (const uint4*)g_q_hi;

    auto prefetch = [&](int stage, int kc) {
        for (int i = t; i < 1536; i += 256) {
            int arr = i >> 9;               // 0 Ah, 1 Al, 2 Bh
            int r   = (i >> 2) & 127;
            int v   = i & 3;
            uint32_t daddr = sb + stage * STG_C + arr * ASZ + r * (SKPH*2) + v * 16;
            if (arr < 2) {
                size_t off = (size_t)sj[r] * 32 + kc * 4 + v;
                cp16(daddr, (arr == 0 ? Fh4 : Fl4) + off, 16);
            } else {
                cp16(daddr, Qh4 + ((size_t)(bn + r) * 32 + kc * 4 + v), 16);
            }
        }
        asm volatile("cp.async.commit_group;" ::: "memory");
    };

    float c[2][8][4];
    #pragma unroll
    for (int mt = 0; mt < 2; mt++)
        #pragma unroll
        for (int nt = 0; nt < 8; nt++)
            #pragma unroll
            for (int q = 0; q < 4; q++) c[mt][nt][q] = 0.f;

    prefetch(0, 0);
    prefetch(1, 1);
    for (int kc = 0; kc < 8; kc++) {
        if (kc < 7) asm volatile("cp.async.wait_group 1;" ::: "memory");
        else        asm volatile("cp.async.wait_group 0;" ::: "memory");
        __syncthreads();
        if (kc + 2 < 8) prefetch((kc + 2) % 3, kc + 2);
        int s = kc % 3;
        uint32_t sAh = sb + s * STG_C;
        uint32_t sAl = sAh + ASZ;
        uint32_t sBh = sAl + ASZ;
        #pragma unroll
        for (int ks = 0; ks < 2; ks++) {
            int kbyte = ks * 32;
            uint32_t ah[2][4], al[2][4], bh[4][4];
            ldsm_A(ah[0], sAh, wm*32,      kbyte, lane);
            ldsm_A(ah[1], sAh, wm*32 + 16, kbyte, lane);
            ldsm_A(al[0], sAl, wm*32,      kbyte, lane);
            ldsm_A(al[1], sAl, wm*32 + 16, kbyte, lane);
            #pragma unroll
            for (int g = 0; g < 4; g++)
                ldsm_B(bh[g], sBh, wn*64 + g*16, kbyte, lane);
            #pragma unroll
            for (int mt = 0; mt < 2; mt++)
                #pragma unroll
                for (int nt = 0; nt < 8; nt++) {
                    const uint32_t* ph = &bh[nt >> 1][(nt & 1) * 2];
                    mma_f16(c[mt][nt], ah[mt], ph);
                    mma_f16(c[mt][nt], al[mt], ph);
                }
        }
    }

    __syncthreads();
    for (int i = t; i < 128 * 32; i += 256) {
        int r = i >> 5, v = i & 31;
        float4 val = ((const float4*)g_B)[(size_t)spid[r] * 64 + (bn >> 2) + v];
        *(float4*)&sBpos[r * 132 + v * 4] = val;
    }
    __syncthreads();

    int slot = blockIdx.x * 2 + wn;
    #pragma unroll
    for (int mt = 0; mt < 2; mt++)
        #pragma unroll
        for (int half = 0; half < 2; half++) {
            int rl = wm*32 + mt*16 + half*8 + (lane >> 2);
            const float* htr = tgt_emb + (size_t)stt[rl] * DIM + bn;
            float p = 0.f;
            #pragma unroll
            for (int nt = 0; nt < 8; nt++) {
                int cl = wn*64 + nt*8 + (lane & 3)*2;
                float y0 = c[mt][nt][half*2 + 0] + sBpos[rl*132 + cl];
                float y1 = c[mt][nt][half*2 + 1] + sBpos[rl*132 + cl + 1];
                p += tanhf(y0) * htr[cl] + tanhf(y1) * htr[cl + 1];
            }
            p += __shfl_xor_sync(0xffffffffu, p, 1);
            p += __shfl_xor_sync(0xffffffffu, p, 2);
            if ((lane & 3) == 0) g_cpart[slot][j0 + rl] = p;
        }
}

// ---------------- select (sums 4 coef partials deterministically) ----------------
__global__ void k_select(const int* __restrict__ agg_src) {
    int tgt = blockIdx.x;
    int d = threadIdx.x;
    float acc = 0.f;
    int rs = g_arowoff[tgt], re = g_arowoff[tgt + 1];
    for (int idx = rs; idx < re; idx++) {
        int j = g_aperm[idx];
        float coef = (g_cpart[0][j] + g_cpart[1][j]) + (g_cpart[2][j] + g_cpart[3][j]);
        acc += coef * g_ft[(size_t)agg_src[j] * DIM + d];
    }
    g_sel_hi[tgt * DIM + d] = __float2half(acc);
}

// ================= scores: single-term fp16 (Ah*Bh), 3-stage pipeline =================
#define STG_S (2 * ASZ)           // 20480
#define SMEM_S (3 * STG_S)        // 61440

__global__ void __launch_bounds__(256) k_scores_mma(float* __restrict__ out) {
    extern __shared__ char sms[];
    uint32_t sb = smem_to_u32(sms);
    int t = threadIdx.x, lane = t & 31, wid = t >> 5;
    int wm = wid & 3, wn = wid >> 2;
    int bm = blockIdx.y * 128;
    int bn = blockIdx.x * 128;
    const int NC = NUM_NODE - 1;

    const uint4* Ah4 = (const uint4*)g_sel_hi;
    const uint4* Bh4 = (const uint4*)g_emb_hi;

    auto prefetch = [&](int stage, int kc) {
        for (int i = t; i < 1024; i += 256) {
            int arr = i >> 9;               // 0 Ah, 1 Bh
            int r   = (i >> 2) & 127;
            int v   = i & 3;
            uint32_t daddr = sb + stage * STG_S + arr * ASZ + r * (SKPH*2) + v * 16;
            if (arr == 0) {
                cp16(daddr, Ah4 + ((size_t)(bm + r) * 32 + kc * 4 + v), 16);
            } else {
                int er = bn + r + 1;
                size_t off = (size_t)(er < NUM_NODE ? er : 0) * 32 + kc * 4 + v;
                cp16(daddr, Bh4 + off, er < NUM_NODE ? 16u : 0u);
            }
        }
        asm volatile("cp.async.commit_group;" ::: "memory");
    };

    float c[2][8][4];
    #pragma unroll
    for (int mt = 0; mt < 2; mt++)
        #pragma unroll
        for (int nt = 0; nt < 8; nt++)
            #pragma unroll
            for (int q = 0; q < 4; q++) c[mt][nt][q] = 0.f;

    prefetch(0, 0);
    prefetch(1, 1);
    for (int kc = 0; kc < 8; kc++) {
        if (kc < 7) asm volatile("cp.async.wait_group 1;" ::: "memory");
        else        asm volatile("cp.async.wait_group 0;" ::: "memory");
        __syncthreads();
        if (kc + 2 < 8) prefetch((kc + 2) % 3, kc + 2);
        int s = kc % 3;
        uint32_t sAh = sb + s * STG_S;
        uint32_t sBh = sAh + ASZ;
        #pragma unroll
        for (int ks = 0; ks < 2; ks++) {
            int kbyte = ks * 32;
            uint32_t ah[2][4], bh[4][4];
            ldsm_A(ah[0], sAh, wm*32,      kbyte, lane);
            ldsm_A(ah[1], sAh, wm*32 + 16, kbyte, lane);
            #pragma unroll
            for (int g = 0; g < 4; g++)
                ldsm_B(bh[g], sBh, wn*64 + g*16, kbyte, lane);
            #pragma unroll
            for (int mt = 0; mt < 2; mt++)
                #pragma unroll
                for (int nt = 0; nt < 8; nt++)
                    mma_f16(c[mt][nt], ah[mt], &bh[nt >> 1][(nt & 1) * 2]);
        }
    }

    #pragma unroll
    for (int mt = 0; mt < 2; mt++) {
        int r0 = bm + wm * 32 + mt * 16 + (lane >> 2);
        #pragma unroll
        for (int nt = 0; nt < 8; nt++) {
            int cc = bn + wn * 64 + nt * 8 + (lane & 3) * 2;
            size_t b0 = (size_t)r0 * NC + cc;
            size_t b1 = (size_t)(r0 + 8) * NC + cc;
            if (cc + 1 < NC) {
                out[b0] = c[mt][nt][0]; out[b0 + 1] = c[mt][nt][1];
                out[b1] = c[mt][nt][2]; out[b1 + 1] = c[mt][nt][3];
            } else if (cc < NC) {
                out[b0] = c[mt][nt][0];
                out[b1] = c[mt][nt][2];
            }
        }
    }
}

// ---------------- launch ----------------
extern "C" void kernel_launch(void* const* d_in, const int* in_sizes, int n_in,
                              void* d_out, int out_size) {
    const int*   iid     = (const int*)d_in[2];
    const int*   pid     = (const int*)d_in[3];
    const int*   tidp    = (const int*)d_in[4];
    const int*   i_src   = (const int*)d_in[5];
    const int*   i_dst   = (const int*)d_in[6];
    const int*   agg_src = (const int*)d_in[7];
    const int*   agg_dst = (const int*)d_in[8];
    const float* emb     = (const float*)d_in[9];
    const float* pos_emb = (const float*)d_in[10];
    const float* tgt_emb = (const float*)d_in[11];
    const float* p_w     = (const float*)d_in[12];
    const float* q_w     = (const float*)d_in[13];
    float* out = (float*)d_out;

    static bool attr_set = false;
    if (!attr_set) {
        cudaFuncSetAttribute(k_scores_mma, cudaFuncAttributeMaxDynamicSharedMemorySize, SMEM_S);
        cudaFuncSetAttribute(k_coef_mma,   cudaFuncAttributeMaxDynamicSharedMemorySize, SMEM_C);
        attr_set = true;
    }

    k_prep    <<<(NUM_NODE * DIM + 255) / 256, 256>>>(emb, q_w);
    k_hist    <<<(E_INT + 255) / 256, 256>>>(i_dst, agg_dst);
    k_scanA   <<<328, 256>>>();
    k_scanB   <<<1, 512>>>();
    k_scanC   <<<328, 256>>>();
    k_scatter <<<(E_INT + 255) / 256, 256>>>(i_dst, i_src, iid, agg_dst);
    k_attn    <<<N_ITEM / 8, 256>>>(iid, emb, p_w);
    k_posB    <<<NPOS, 256>>>(pos_emb, q_w);
    dim3 gc(2, N_ITEM / 128);
    k_coef_mma<<<gc, 256, SMEM_C>>>(agg_src, pid, agg_dst, tidp, tgt_emb);
    k_select  <<<N_TGT, 256>>>(agg_src);
    dim3 gs((NUM_NODE - 1 + 127) / 128, N_TGT / 128);
    k_scores_mma<<<gs, 256, SMEM_S>>>(out);
}

// round 9
// speedup vs baseline: 4.3818x; 1.1402x over previous
#include <cuda_runtime.h>
#include <cuda_fp16.h>
#include <cstdint>
#include <cstddef>

#define N_ITEM 81920
#define E_INT 327680
#define N_TGT 2048
#define NUM_NODE 50000
#define DIM 256
#define NPOS 200
#define ALPHA 0.2f

// ---------------- device scratch (static, no allocation) ----------------
__device__ __align__(16) float g_ft[(size_t)N_ITEM * DIM];
__device__ __align__(16) __half g_ft_hi[(size_t)N_ITEM * DIM];
__device__ int   g_deg[N_ITEM];
__device__ int   g_rowoff[N_ITEM + 1];
__device__ int   g_cursor[N_ITEM];
__device__ int   g_esrc[E_INT];          // src row id (iid[i_src[e]]) sorted by dst
__device__ int   g_adeg[N_TGT];
__device__ int   g_arowoff[N_TGT + 1];
__device__ int   g_acursor[N_TGT];
__device__ int   g_aperm[N_ITEM];
__device__ int   g_bsum[328];
__device__ int   g_boff[328];
__device__ __align__(16) float g_B[NPOS * DIM];
__device__ float g_cpart[4][N_ITEM];     // coef partials: [ctaN*2 + warpN][row]
__device__ __align__(16) __half g_emb_hi[(size_t)NUM_NODE * DIM];
__device__ __align__(16) __half g_q_hi[DIM * DIM];
__device__ __align__(16) __half g_sel_hi[N_TGT * DIM];

__device__ __forceinline__ uint32_t smem_to_u32(const void* p) {
    uint32_t a;
    asm("{ .reg .u64 t; cvta.to.shared.u64 t, %1; cvt.u32.u64 %0, t; }" : "=r"(a) : "l"(p));
    return a;
}
__device__ __forceinline__ void cp16(uint32_t daddr, const void* src, uint32_t srcsize) {
    asm volatile("cp.async.cg.shared.global [%0], [%1], 16, %2;"
                 :: "r"(daddr), "l"(src), "r"(srcsize) : "memory");
}
__device__ __forceinline__ void mma_f16(float* c, const uint32_t* a, const uint32_t* b) {
    asm volatile("mma.sync.aligned.m16n8k16.row.col.f32.f16.f16.f32 "
                 "{%0,%1,%2,%3}, {%4,%5,%6,%7}, {%8,%9}, {%0,%1,%2,%3};"
                 : "+f"(c[0]), "+f"(c[1]), "+f"(c[2]), "+f"(c[3])
                 : "r"(a[0]), "r"(a[1]), "r"(a[2]), "r"(a[3]), "r"(b[0]), "r"(b[1]));
}
__device__ __forceinline__ void ldsm4(uint32_t* r, uint32_t addr) {
    asm volatile("ldmatrix.sync.aligned.m8n8.x4.shared.b16 {%0,%1,%2,%3}, [%4];"
                 : "=r"(r[0]), "=r"(r[1]), "=r"(r[2]), "=r"(r[3]) : "r"(addr));
}
// A 16x16 fp16 tile (row-major rows, 80B row stride) -> a-frag {a0,a1,a2,a3}
__device__ __forceinline__ void ldsm_A(uint32_t* r4, uint32_t base, int row0, int kbyte, int lane) {
    int m = lane >> 3, rr = lane & 7;
    uint32_t addr = base + (uint32_t)(row0 + ((m & 1) << 3) + rr) * 80u + kbyte + ((m >> 1) << 4);
    ldsm4(r4, addr);
}
// B: 16 n-rows x 16 k (row-major n rows, 80B stride) -> {b0(nt0),b1(nt0),b0(nt1),b1(nt1)}
__device__ __forceinline__ void ldsm_B(uint32_t* r4, uint32_t base, int n0, int kbyte, int lane) {
    int m = lane >> 3, rr = lane & 7;
    uint32_t addr = base + (uint32_t)(n0 + ((m >> 1) << 3) + rr) * 80u + kbyte + ((m & 1) << 4);
    ldsm4(r4, addr);
}

// ---------------- fused prep: zero counters + fp16 splits ----------------
__global__ void k_prep(const float* __restrict__ emb, const float* __restrict__ q_w) {
    size_t i = (size_t)blockIdx.x * blockDim.x + threadIdx.x;
    if (i < (size_t)NUM_NODE * DIM) g_emb_hi[i] = __float2half(emb[i]);
    if (i < DIM * DIM) {
        int d = (int)(i >> 8), k = (int)(i & 255);
        g_q_hi[i] = __float2half(q_w[(size_t)d * (2 * DIM) + k]);
    }
    if (i < N_ITEM) g_deg[i] = 0;
    if (i < N_TGT)  g_adeg[i] = 0;
}

// ---------------- histogram ----------------
__global__ void k_hist(const int* __restrict__ i_dst, const int* __restrict__ agg_dst) {
    int i = blockIdx.x * blockDim.x + threadIdx.x;
    if (i < E_INT)  atomicAdd(&g_deg[i_dst[i]], 1);
    if (i < N_ITEM) atomicAdd(&g_adeg[agg_dst[i]], 1);
}

// ---------------- 3-phase scan: blocks 0..319 item chunks, 320..327 tgt chunks ----------------
__global__ void __launch_bounds__(256) k_scanA() {
    int b = blockIdx.x, t = threadIdx.x;
    __shared__ int s[256];
    int v = (b < 320) ? g_deg[b * 256 + t] : g_adeg[(b - 320) * 256 + t];
    s[t] = v;
    __syncthreads();
    #pragma unroll
    for (int o = 128; o; o >>= 1) {
        if (t < o) s[t] += s[t + o];
        __syncthreads();
    }
    if (t == 0) g_bsum[b] = s[0];
}
__global__ void __launch_bounds__(512) k_scanB() {
    __shared__ int s[512];
    int t = threadIdx.x;
    int v = (t < 320) ? g_bsum[t] : 0;
    s[t] = v;
    __syncthreads();
    for (int o = 1; o < 512; o <<= 1) {
        int u = (t >= o) ? s[t - o] : 0;
        __syncthreads();
        if (t >= o) s[t] += u;
        __syncthreads();
    }
    if (t < 320) g_boff[t] = s[t] - v;      // exclusive
    if (t == 0) {
        int run = 0;
        #pragma unroll
        for (int i = 0; i < 8; i++) { g_boff[320 + i] = run; run += g_bsum[320 + i]; }
    }
}
__global__ void __launch_bounds__(256) k_scanC() {
    int b = blockIdx.x, t = threadIdx.x;
    __shared__ int s[256];
    int base = g_boff[b];
    int idx, v;
    if (b < 320) { idx = b * 256 + t; v = g_deg[idx]; }
    else         { idx = (b - 320) * 256 + t; v = g_adeg[idx]; }
    s[t] = v;
    __syncthreads();
    for (int o = 1; o < 256; o <<= 1) {
        int u = (t >= o) ? s[t - o] : 0;
        __syncthreads();
        if (t >= o) s[t] += u;
        __syncthreads();
    }
    int excl = base + s[t] - v;
    if (b < 320) { g_rowoff[idx] = excl; g_cursor[idx] = excl; }
    else         { g_arowoff[idx] = excl; g_acursor[idx] = excl; }
    if (b == 0 && t == 0) { g_rowoff[N_ITEM] = E_INT; g_arowoff[N_TGT] = N_ITEM; }
}

// ---------------- scatter (stores src ROW id directly for attn) ----------------
__global__ void k_scatter(const int* __restrict__ i_dst, const int* __restrict__ i_src,
                          const int* __restrict__ iid, const int* __restrict__ agg_dst) {
    int i = blockIdx.x * blockDim.x + threadIdx.x;
    if (i < E_INT) {
        int d = i_dst[i];
        int p = atomicAdd(&g_cursor[d], 1);
        g_esrc[p] = iid[i_src[i]];
    }
    if (i < N_ITEM) {
        int d = agg_dst[i];
        g_aperm[atomicAdd(&g_acursor[d], 1)] = i;
    }
}

// ---------------- single-pass attention, edge loop unrolled x2 ----------------
__global__ void __launch_bounds__(256) k_attn(const int* __restrict__ iid,
                                              const float* __restrict__ emb,
                                              const float* __restrict__ p_w) {
    int gw   = (blockIdx.x * blockDim.x + threadIdx.x) >> 5;
    int lane = threadIdx.x & 31;
    if (gw >= N_ITEM) return;
    int v = gw;
    const float4* embv = (const float4*)emb;
    int c0 = lane * 2;
    size_t rv = (size_t)iid[v] * (DIM / 4);
    float4 hd0 = embv[rv + c0];
    float4 hd1 = embv[rv + c0 + 1];
    float4 pw0 = ((const float4*)p_w)[c0];
    float4 pw1 = ((const float4*)p_w)[c0 + 1];
    hd0.x *= pw0.x; hd0.y *= pw0.y; hd0.z *= pw0.z; hd0.w *= pw0.w;
    hd1.x *= pw1.x; hd1.y *= pw1.y; hd1.z *= pw1.z; hd1.w *= pw1.w;
    int rs = g_rowoff[v], re = g_rowoff[v + 1];

    float den = 0.f;
    float4 a0 = make_float4(0.f,0.f,0.f,0.f), a1 = make_float4(0.f,0.f,0.f,0.f);
    int idx = rs;
    for (; idx + 1 < re; idx += 2) {
        size_t ruA = (size_t)g_esrc[idx] * (DIM / 4);
        size_t ruB = (size_t)g_esrc[idx + 1] * (DIM / 4);
        float4 sA0 = embv[ruA + c0], sA1 = embv[ruA + c0 + 1];
        float4 sB0 = embv[ruB + c0], sB1 = embv[ruB + c0 + 1];
        float pA = sA0.x*hd0.x + sA0.y*hd0.y + sA0.z*hd0.z + sA0.w*hd0.w
                 + sA1.x*hd1.x + sA1.y*hd1.y + sA1.z*hd1.z + sA1.w*hd1.w;
        float pB = sB0.x*hd0.x + sB0.y*hd0.y + sB0.z*hd0.z + sB0.w*hd0.w
                 + sB1.x*hd1.x + sB1.y*hd1.y + sB1.z*hd1.z + sB1.w*hd1.w;
        #pragma unroll
        for (int o = 16; o; o >>= 1) {
            pA += __shfl_xor_sync(0xffffffffu, pA, o);
            pB += __shfl_xor_sync(0xffffffffu, pB, o);
        }
        pA = (pA >= 0.f) ? pA : ALPHA * pA;
        pB = (pB >= 0.f) ? pB : ALPHA * pB;
        float eA = __expf(pA), eB = __expf(pB);
        den += eA + eB;
        a0.x += eA*sA0.x + eB*sB0.x; a0.y += eA*sA0.y + eB*sB0.y;
        a0.z += eA*sA0.z + eB*sB0.z; a0.w += eA*sA0.w + eB*sB0.w;
        a1.x += eA*sA1.x + eB*sB1.x; a1.y += eA*sA1.y + eB*sB1.y;
        a1.z += eA*sA1.z + eB*sB1.z; a1.w += eA*sA1.w + eB*sB1.w;
    }
    if (idx < re) {
        size_t ru = (size_t)g_esrc[idx] * (DIM / 4);
        float4 hs0 = embv[ru + c0], hs1 = embv[ru + c0 + 1];
        float p = hs0.x*hd0.x + hs0.y*hd0.y + hs0.z*hd0.z + hs0.w*hd0.w
                + hs1.x*hd1.x + hs1.y*hd1.y + hs1.z*hd1.z + hs1.w*hd1.w;
        #pragma unroll
        for (int o = 16; o; o >>= 1) p += __shfl_xor_sync(0xffffffffu, p, o);
        p = (p >= 0.f) ? p : ALPHA * p;
        float ex = __expf(p);
        den += ex;
        a0.x += ex*hs0.x; a0.y += ex*hs0.y; a0.z += ex*hs0.z; a0.w += ex*hs0.w;
        a1.x += ex*hs1.x; a1.y += ex*hs1.y; a1.z += ex*hs1.z; a1.w += ex*hs1.w;
    }
    float inv = 1.f / fmaxf(den, 1e-12f);
    float o[8] = { a0.x*inv, a0.y*inv, a0.z*inv, a0.w*inv,
                   a1.x*inv, a1.y*inv, a1.z*inv, a1.w*inv };
    ((float4*)g_ft)[(size_t)v*(DIM/4) + c0]     = make_float4(o[0], o[1], o[2], o[3]);
    ((float4*)g_ft)[(size_t)v*(DIM/4) + c0 + 1] = make_float4(o[4], o[5], o[6], o[7]);
    union { __half h[8]; uint4 u; } ph;
    #pragma unroll
    for (int q = 0; q < 8; q++) ph.h[q] = __float2half(o[q]);
    ((uint4*)g_ft_hi)[(size_t)v * 32 + lane] = ph.u;
}

// ---------------- B = pos_emb @ q_w[:,256:].T ----------------
__global__ void k_posB(const float* __restrict__ pos_emb, const float* __restrict__ q_w) {
    int p = blockIdx.x, d = threadIdx.x;
    __shared__ float sp[DIM];
    sp[d] = pos_emb[p * DIM + d];
    __syncthreads();
    const float4* q4 = (const float4*)(q_w + (size_t)d * (2 * DIM) + DIM);
    float acc = 0.f;
    #pragma unroll 8
    for (int k = 0; k < DIM / 4; k++) {
        float4 q = q4[k];
        acc += sp[4*k]*q.x + sp[4*k+1]*q.y + sp[4*k+2]*q.z + sp[4*k+3]*q.w;
    }
    g_B[p * DIM + d] = acc;
}

// ================= k_coef via mma (single-term fp16: ft_hi * q_hi) =================
#define SKPH 40
#define ASZ (128 * SKPH * 2)      // 10240 B per array per stage
#define STG_C (2 * ASZ)           // 20480 (Ah, Bh)
#define OFF_SJ   (3 * STG_C)      // 61440
#define OFF_SPID (OFF_SJ + 512)
#define OFF_ST   (OFF_SPID + 512)
#define SMEM_C   (OFF_ST + 512)   // 62976

__global__ void __launch_bounds__(256) k_coef_mma(const int* __restrict__ agg_src,
                                                  const int* __restrict__ pid,
                                                  const int* __restrict__ agg_dst,
                                                  const int* __restrict__ tid,
                                                  const float* __restrict__ tgt_emb) {
    extern __shared__ char smc[];
    uint32_t sb = smem_to_u32(smc);
    int* sj   = (int*)(smc + OFF_SJ);
    int* spid = (int*)(smc + OFF_SPID);
    int* stt  = (int*)(smc + OFF_ST);

    int t = threadIdx.x, lane = t & 31, wid = t >> 5;
    int wm = wid & 3, wn = wid >> 2;
    int bn = blockIdx.x * 128;               // d-tile (0 or 128)
    int j0 = blockIdx.y * 128;

    if (t < 128) {
        sj[t]   = agg_src[j0 + t];
        spid[t] = pid[j0 + t];
        stt[t]  = tid[agg_dst[j0 + t]];
    }
    __syncthreads();

    const uint4* Fh4 = (const uint4*)g_ft_hi;
    const uint4* Qh4 = (const uint4*)g_q_hi;

    auto prefetch = [&](int stage, int kc) {
        for (int i = t; i < 1024; i += 256) {
            int arr = i >> 9;               // 0 Ah, 1 Bh
            int r   = (i >> 2) & 127;
            int v   = i & 3;
            uint32_t daddr = sb + stage * STG_C + arr * ASZ + r * (SKPH*2) + v * 16;
            if (arr == 0) {
                cp16(daddr, Fh4 + ((size_t)sj[r] * 32 + kc * 4 + v), 16);
            } else {
                cp16(daddr, Qh4 + ((size_t)(bn + r) * 32 + kc * 4 + v), 16);
            }
        }
        asm volatile("cp.async.commit_group;" ::: "memory");
    };

    float c[2][8][4];
    #pragma unroll
    for (int mt = 0; mt < 2; mt++)
        #pragma unroll
        for (int nt = 0; nt < 8; nt++)
            #pragma unroll
            for (int q = 0; q < 4; q++) c[mt][nt][q] = 0.f;

    prefetch(0, 0);
    prefetch(1, 1);
    for (int kc = 0; kc < 8; kc++) {
        if (kc < 7) asm volatile("cp.async.wait_group 1;" ::: "memory");
        else        asm volatile("cp.async.wait_group 0;" ::: "memory");
        __syncthreads();
        if (kc + 2 < 8) prefetch((kc + 2) % 3, kc + 2);
        int s = kc % 3;
        uint32_t sAh = sb + s * STG_C;
        uint32_t sBh = sAh + ASZ;
        #pragma unroll
        for (int ks = 0; ks < 2; ks++) {
            int kbyte = ks * 32;
            uint32_t ah[2][4], bh[4][4];
            ldsm_A(ah[0], sAh, wm*32,      kbyte, lane);
            ldsm_A(ah[1], sAh, wm*32 + 16, kbyte, lane);
            #pragma unroll
            for (int g = 0; g < 4; g++)
                ldsm_B(bh[g], sBh, wn*64 + g*16, kbyte, lane);
            #pragma unroll
            for (int mt = 0; mt < 2; mt++)
                #pragma unroll
                for (int nt = 0; nt < 8; nt++)
                    mma_f16(c[mt][nt], ah[mt], &bh[nt >> 1][(nt & 1) * 2]);
        }
    }

    // epilogue: tanh(Y + Bpos) dot ht, direct L2-resident g_B reads
    int slot = blockIdx.x * 2 + wn;
    #pragma unroll
    for (int mt = 0; mt < 2; mt++)
        #pragma unroll
        for (int half = 0; half < 2; half++) {
            int rl = wm*32 + mt*16 + half*8 + (lane >> 2);
            const float* Brow = g_B + (size_t)spid[rl] * DIM + bn;
            const float* htr  = tgt_emb + (size_t)stt[rl] * DIM + bn;
            float p = 0.f;
            #pragma unroll
            for (int nt = 0; nt < 8; nt++) {
                int cl = wn*64 + nt*8 + (lane & 3)*2;
                float y0 = c[mt][nt][half*2 + 0] + Brow[cl];
                float y1 = c[mt][nt][half*2 + 1] + Brow[cl + 1];
                p += tanhf(y0) * htr[cl] + tanhf(y1) * htr[cl + 1];
            }
            p += __shfl_xor_sync(0xffffffffu, p, 1);
            p += __shfl_xor_sync(0xffffffffu, p, 2);
            if ((lane & 3) == 0) g_cpart[slot][j0 + rl] = p;
        }
}

// ---------------- select (sums 4 coef partials deterministically) ----------------
__global__ void k_select(const int* __restrict__ agg_src) {
    int tgt = blockIdx.x;
    int d = threadIdx.x;
    float acc = 0.f;
    int rs = g_arowoff[tgt], re = g_arowoff[tgt + 1];
    for (int idx = rs; idx < re; idx++) {
        int j = g_aperm[idx];
        float coef = (g_cpart[0][j] + g_cpart[1][j]) + (g_cpart[2][j] + g_cpart[3][j]);
        acc += coef * g_ft[(size_t)agg_src[j] * DIM + d];
    }
    g_sel_hi[tgt * DIM + d] = __float2half(acc);
}

// ================= scores: single-term fp16 (Ah*Bh), 3-stage pipeline =================
#define STG_S (2 * ASZ)           // 20480
#define SMEM_S (3 * STG_S)        // 61440

__global__ void __launch_bounds__(256) k_scores_mma(float* __restrict__ out) {
    extern __shared__ char sms[];
    uint32_t sb = smem_to_u32(sms);
    int t = threadIdx.x, lane = t & 31, wid = t >> 5;
    int wm = wid & 3, wn = wid >> 2;
    int bm = blockIdx.y * 128;
    int bn = blockIdx.x * 128;
    const int NC = NUM_NODE - 1;

    const uint4* Ah4 = (const uint4*)g_sel_hi;
    const uint4* Bh4 = (const uint4*)g_emb_hi;

    auto prefetch = [&](int stage, int kc) {
        for (int i = t; i < 1024; i += 256) {
            int arr = i >> 9;               // 0 Ah, 1 Bh
            int r   = (i >> 2) & 127;
            int v   = i & 3;
            uint32_t daddr = sb + stage * STG_S + arr * ASZ + r * (SKPH*2) + v * 16;
            if (arr == 0) {
                cp16(daddr, Ah4 + ((size_t)(bm + r) * 32 + kc * 4 + v), 16);
            } else {
                int er = bn + r + 1;
                size_t off = (size_t)(er < NUM_NODE ? er : 0) * 32 + kc * 4 + v;
                cp16(daddr, Bh4 + off, er < NUM_NODE ? 16u : 0u);
            }
        }
        asm volatile("cp.async.commit_group;" ::: "memory");
    };

    float c[2][8][4];
    #pragma unroll
    for (int mt = 0; mt < 2; mt++)
        #pragma unroll
        for (int nt = 0; nt < 8; nt++)
            #pragma unroll
            for (int q = 0; q < 4; q++) c[mt][nt][q] = 0.f;

    prefetch(0, 0);
    prefetch(1, 1);
    for (int kc = 0; kc < 8; kc++) {
        if (kc < 7) asm volatile("cp.async.wait_group 1;" ::: "memory");
        else        asm volatile("cp.async.wait_group 0;" ::: "memory");
        __syncthreads();
        if (kc + 2 < 8) prefetch((kc + 2) % 3, kc + 2);
        int s = kc % 3;
        uint32_t sAh = sb + s * STG_S;
        uint32_t sBh = sAh + ASZ;
        #pragma unroll
        for (int ks = 0; ks < 2; ks++) {
            int kbyte = ks * 32;
            uint32_t ah[2][4], bh[4][4];
            ldsm_A(ah[0], sAh, wm*32,      kbyte, lane);
            ldsm_A(ah[1], sAh, wm*32 + 16, kbyte, lane);
            #pragma unroll
            for (int g = 0; g < 4; g++)
                ldsm_B(bh[g], sBh, wn*64 + g*16, kbyte, lane);
            #pragma unroll
            for (int mt = 0; mt < 2; mt++)
                #pragma unroll
                for (int nt = 0; nt < 8; nt++)
                    mma_f16(c[mt][nt], ah[mt], &bh[nt >> 1][(nt & 1) * 2]);
        }
    }

    #pragma unroll
    for (int mt = 0; mt < 2; mt++) {
        int r0 = bm + wm * 32 + mt * 16 + (lane >> 2);
        #pragma unroll
        for (int nt = 0; nt < 8; nt++) {
            int cc = bn + wn * 64 + nt * 8 + (lane & 3) * 2;
            size_t b0 = (size_t)r0 * NC + cc;
            size_t b1 = (size_t)(r0 + 8) * NC + cc;
            if (cc + 1 < NC) {
                out[b0] = c[mt][nt][0]; out[b0 + 1] = c[mt][nt][1];
                out[b1] = c[mt][nt][2]; out[b1 + 1] = c[mt][nt][3];
            } else if (cc < NC) {
                out[b0] = c[mt][nt][0];
                out[b1] = c[mt][nt][2];
            }
        }
    }
}

// ---------------- launch ----------------
extern "C" void kernel_launch(void* const* d_in, const int* in_sizes, int n_in,
                              void* d_out, int out_size) {
    const int*   iid     = (const int*)d_in[2];
    const int*   pid     = (const int*)d_in[3];
    const int*   tidp    = (const int*)d_in[4];
    const int*   i_src   = (const int*)d_in[5];
    const int*   i_dst   = (const int*)d_in[6];
    const int*   agg_src = (const int*)d_in[7];
    const int*   agg_dst = (const int*)d_in[8];
    const float* emb     = (const float*)d_in[9];
    const float* pos_emb = (const float*)d_in[10];
    const float* tgt_emb = (const float*)d_in[11];
    const float* p_w     = (const float*)d_in[12];
    const float* q_w     = (const float*)d_in[13];
    float* out = (float*)d_out;

    static bool attr_set = false;
    if (!attr_set) {
        cudaFuncSetAttribute(k_scores_mma, cudaFuncAttributeMaxDynamicSharedMemorySize, SMEM_S);
        cudaFuncSetAttribute(k_coef_mma,   cudaFuncAttributeMaxDynamicSharedMemorySize, SMEM_C);
        attr_set = true;
    }

    k_prep    <<<(NUM_NODE * DIM + 255) / 256, 256>>>(emb, q_w);
    k_hist    <<<(E_INT + 255) / 256, 256>>>(i_dst, agg_dst);
    k_scanA   <<<328, 256>>>();
    k_scanB   <<<1, 512>>>();
    k_scanC   <<<328, 256>>>();
    k_scatter <<<(E_INT + 255) / 256, 256>>>(i_dst, i_src, iid, agg_dst);
    k_attn    <<<N_ITEM / 8, 256>>>(iid, emb, p_w);
    k_posB    <<<NPOS, 256>>>(pos_emb, q_w);
    dim3 gc(2, N_ITEM / 128);
    k_coef_mma<<<gc, 256, SMEM_C>>>(agg_src, pid, agg_dst, tidp, tgt_emb);
    k_select  <<<N_TGT, 256>>>(agg_src);
    dim3 gs((NUM_NODE - 1 + 127) / 128, N_TGT / 128);
    k_scores_mma<<<gs, 256, SMEM_S>>>(out);
}